// round 9
// baseline (speedup 1.0000x reference)
#include <cuda_runtime.h>
#include <cuda_fp16.h>
#include <cstdint>

#define N_NODES 50000
#define IN_DIM  7688
#define HID     200
#define OUT_DIM 8
#define N_EDGES 1600000

// ---------------- scratch (device globals; no allocation allowed) -------------
__device__ float  g_dis[N_NODES];
__device__ int    g_cnt[N_NODES];
__device__ int    g_off[N_NODES + 1];
__device__ int    g_cur[N_NODES];
__device__ int    g_csr_src[N_EDGES];
__device__ float  g_csr_w[N_EDGES];
__device__ __half g_W1h[(size_t)HID * IN_DIM];      // W1^T in fp16, [n][k]
__device__ float  g_H1[(size_t)N_NODES * HID];
__device__ float  g_h[(size_t)N_NODES * HID];
__device__ float  g_H2[(size_t)N_NODES * OUT_DIM];
__device__ int    g_is64;

// ---------------- helpers ----------------------------------------------------
__device__ __forceinline__ int edge_at(const void* ei, size_t pos, int is64) {
    if (is64) return (int)((const long long*)ei)[pos];
    return ((const int*)ei)[pos];
}

__device__ __forceinline__ uint32_t smem_u32(const void* p) {
    uint32_t a;
    asm("{ .reg .u64 t; cvta.to.shared.u64 t, %1; cvt.u32.u64 %0, t; }"
        : "=r"(a) : "l"(p));
    return a;
}

__device__ __forceinline__ void cp16(uint32_t saddr, const void* g, int sz) {
    asm volatile("cp.async.cg.shared.global [%0], [%1], 16, %2;\n"
                 :: "r"(saddr), "l"(g), "r"(sz));
}

#define LDSM4(r0, r1, r2, r3, a)                                               \
    asm volatile("ldmatrix.sync.aligned.m8n8.x4.shared.b16 {%0,%1,%2,%3},[%4];"\
                 : "=r"(r0), "=r"(r1), "=r"(r2), "=r"(r3) : "r"(a))

#define LDSM2(r0, r1, a)                                                       \
    asm volatile("ldmatrix.sync.aligned.m8n8.x2.shared.b16 {%0,%1},[%2];"      \
                 : "=r"(r0), "=r"(r1) : "r"(a))

#define MMA16816(c, a, b)                                                      \
    asm volatile(                                                              \
        "mma.sync.aligned.m16n8k16.row.col.f32.f16.f16.f32 "                   \
        "{%0,%1,%2,%3},{%4,%5,%6,%7},{%8,%9},{%0,%1,%2,%3};\n"                 \
        : "+f"((c)[0]), "+f"((c)[1]), "+f"((c)[2]), "+f"((c)[3])               \
        : "r"((a)[0]), "r"((a)[1]), "r"((a)[2]), "r"((a)[3]),                  \
          "r"((b)[0]), "r"((b)[1]))

// ---------------- dtype detection --------------------------------------------
__global__ void detect_kernel(const unsigned* __restrict__ w, int n_check) {
    __shared__ int bad;
    if (threadIdx.x == 0) bad = 0;
    __syncthreads();
    int local = 0;
    for (int i = threadIdx.x; i < n_check; i += blockDim.x)
        if (w[2 * i + 1] != 0u) local = 1;
    if (local) bad = 1;
    __syncthreads();
    if (threadIdx.x == 0) g_is64 = bad ? 0 : 1;
}

// ---------------- degree + histogram init ------------------------------------
__global__ void init_kernel() {
    int i = blockIdx.x * blockDim.x + threadIdx.x;
    if (i < N_NODES) { g_dis[i] = 1.0f; g_cnt[i] = 0; }
}

// ---------------- W1 transpose + fp16 convert --------------------------------
__global__ void w1t_kernel(const float* __restrict__ W1) {
    __shared__ float tile[32][33];
    int kb = blockIdx.y * 32, nb = blockIdx.x * 32;
    for (int j = threadIdx.y; j < 32; j += 8) {
        int k = kb + j, n = nb + threadIdx.x;
        tile[j][threadIdx.x] =
            (k < IN_DIM && n < HID) ? W1[(size_t)k * HID + n] : 0.f;
    }
    __syncthreads();
    for (int j = threadIdx.y; j < 32; j += 8) {
        int n = nb + j, k = kb + threadIdx.x;
        if (n < HID && k < IN_DIM)
            g_W1h[(size_t)n * IN_DIM + k] = __float2half_rn(tile[threadIdx.x][j]);
    }
}

// ---------------- GEMM1: 64x200 CTA, A 2-ahead reg prefetch, B 3-stage -------
#define G1T   160
#define G1_BM 64
#define G1_NT 241
#define SMA_BYTES (G1_BM * 64)     // 4096 per buffer
#define SMB_BYTES (200 * 64)       // 12800 per buffer

__global__ __launch_bounds__(G1T, 2)
void gemm1_kernel(const float* __restrict__ X) {
    __shared__ __align__(16) unsigned char smA[2][SMA_BYTES];
    __shared__ __align__(16) unsigned char smB[3][SMB_BYTES];

    const int tid  = threadIdx.x;
    const int lane = tid & 31;
    const int warp = tid >> 5;          // 0..4 = n-slot
    const int gid  = lane >> 2;
    const int tig  = lane & 3;
    const int wn   = warp;
    const int m0   = blockIdx.x * G1_BM;

    // A fill mapping: 64 rows x 4 chunks(16B) = 256 chunks over 160 threads
    const int i0 = tid;
    const int i1 = tid + G1T;
    const int m_0 = i0 >> 2, c_0 = i0 & 3;
    const int m_1 = i1 >> 2, c_1 = i1 & 3;
    const bool has1 = (i1 < G1_BM * 4);
    const uint32_t dst0 = (uint32_t)(m_0 * 64 + ((c_0 ^ ((m_0 >> 1) & 3)) << 4));
    const uint32_t dst1 = (uint32_t)(m_1 * 64 + ((c_1 ^ ((m_1 >> 1) & 3)) << 4));
    const bool okm0 = (m0 + m_0) < N_NODES;
    const bool okm1 = has1 && ((m0 + m_1) < N_NODES);
    const float* rp0 = X + (size_t)(okm0 ? (m0 + m_0) : 0) * IN_DIM + c_0 * 8;
    const float* rp1 = X + (size_t)(okm1 ? (m0 + m_1) : 0) * IN_DIM + c_1 * 8;

    const uint32_t smA0 = smem_u32(smA[0]);
    const uint32_t smB0 = smem_u32(smB[0]);

    // two register sets for A (2-tile-ahead prefetch)
    float4 v[2][4];
    auto ldgA = [&](int k0, int set) {
        const float4 z = make_float4(0.f, 0.f, 0.f, 0.f);
        bool k_ok0 = (k0 + c_0 * 8 + 8) <= IN_DIM;
        bool k_ok1 = (k0 + c_1 * 8 + 8) <= IN_DIM;
        if (okm0 && k_ok0) {
            v[set][0] = *reinterpret_cast<const float4*>(rp0 + k0);
            v[set][1] = *reinterpret_cast<const float4*>(rp0 + k0 + 4);
        } else { v[set][0] = z; v[set][1] = z; }
        if (okm1 && k_ok1) {
            v[set][2] = *reinterpret_cast<const float4*>(rp1 + k0);
            v[set][3] = *reinterpret_cast<const float4*>(rp1 + k0 + 4);
        } else { v[set][2] = z; v[set][3] = z; }
    };
    auto stsA = [&](int set, uint32_t abase) {
        __half2 h0 = __floats2half2_rn(v[set][0].x, v[set][0].y);
        __half2 h1 = __floats2half2_rn(v[set][0].z, v[set][0].w);
        __half2 h2 = __floats2half2_rn(v[set][1].x, v[set][1].y);
        __half2 h3 = __floats2half2_rn(v[set][1].z, v[set][1].w);
        *reinterpret_cast<uint4*>(&((unsigned char*)smA[0])[abase + dst0]) =
            make_uint4(*(uint32_t*)&h0, *(uint32_t*)&h1,
                       *(uint32_t*)&h2, *(uint32_t*)&h3);
        if (has1) {
            __half2 g0 = __floats2half2_rn(v[set][2].x, v[set][2].y);
            __half2 g1 = __floats2half2_rn(v[set][2].z, v[set][2].w);
            __half2 g2 = __floats2half2_rn(v[set][3].x, v[set][3].y);
            __half2 g3 = __floats2half2_rn(v[set][3].z, v[set][3].w);
            *reinterpret_cast<uint4*>(&((unsigned char*)smA[0])[abase + dst1]) =
                make_uint4(*(uint32_t*)&g0, *(uint32_t*)&g1,
                           *(uint32_t*)&g2, *(uint32_t*)&g3);
        }
    };
    auto cpB = [&](int k0, int bufB) {
        const uint32_t bb = smB0 + (uint32_t)bufB * SMB_BYTES;
        for (int j = tid; j < 800; j += G1T) {
            int n = j >> 2, c = j & 3;
            int ok = (k0 + c * 8 + 8) <= IN_DIM;
            const __half* src = g_W1h + (size_t)n * IN_DIM + (ok ? (k0 + c * 8) : 0);
            cp16(bb + n * 64 + ((c ^ ((n >> 1) & 3)) << 4), src, ok ? 16 : 0);
        }
        asm volatile("cp.async.commit_group;\n");
    };

    // per-thread fragment offsets (buffer-relative)
    uint32_t aRow[4], bCol[5];
#pragma unroll
    for (int mi = 0; mi < 4; mi++)
        aRow[mi] = (uint32_t)((mi * 16 + (lane & 15)) * 64);
#pragma unroll
    for (int ni = 0; ni < 5; ni++)
        bCol[ni] = (uint32_t)((wn * 40 + ni * 8 + (lane & 7)) * 64);
    const int selA = ((lane & 15) >> 1) & 3;
    const int khalfA = lane >> 4;
    const int selB = ((lane & 7) >> 1) & 3;
    const int bhalfB = (lane >> 3) & 1;

    float c[4][5][4];
#pragma unroll
    for (int mi = 0; mi < 4; mi++)
#pragma unroll
        for (int ni = 0; ni < 5; ni++)
#pragma unroll
            for (int r = 0; r < 4; r++) c[mi][ni][r] = 0.0f;

    // ---- prologue: A tiles 0,1 in regs; B groups 0,1 committed --------------
    ldgA(0, 0);
    ldgA(32, 1);
    cpB(0, 0);
    cpB(32, 1);
    stsA(0, 0);                                    // A(0) -> Abuf0
    asm volatile("cp.async.wait_group 1;\n");      // B(0) ready
    __syncthreads();

    int bB = 0;                                     // B buffer for tile t
    for (int t = 0; t < G1_NT; t++) {
        const int bufA = t & 1;
        const bool p2 = (t + 2) < G1_NT;
        if (p2) {
            ldgA((t + 2) * 32, bufA);               // regs[bufA] free (A(t) stored)
            int bB2 = bB + 2; if (bB2 >= 3) bB2 -= 3;
            cpB((t + 2) * 32, bB2);
        } else {
            asm volatile("cp.async.commit_group;\n");  // keep group count aligned
        }

        const uint32_t abase = (uint32_t)bufA * SMA_BYTES;           // byte off in smA
        const uint32_t bbase = smB0 + (uint32_t)bB * SMB_BYTES;
        const uint32_t asm0 = smA0 + abase;

        uint32_t a[2][4][4], b[2][5][2];
#pragma unroll
        for (int ks = 0; ks < 2; ks++) {
            uint32_t aoff = (uint32_t)(((ks * 2 + khalfA) ^ selA) << 4);
            uint32_t boff = (uint32_t)(((ks * 2 + bhalfB) ^ selB) << 4);
#pragma unroll
            for (int mi = 0; mi < 4; mi++)
                LDSM4(a[ks][mi][0], a[ks][mi][1], a[ks][mi][2], a[ks][mi][3],
                      asm0 + aRow[mi] + aoff);
#pragma unroll
            for (int ni = 0; ni < 5; ni++)
                LDSM2(b[ks][ni][0], b[ks][ni][1], bbase + bCol[ni] + boff);
        }
#pragma unroll
        for (int ks = 0; ks < 2; ks++)
#pragma unroll
            for (int mi = 0; mi < 4; mi++)
#pragma unroll
                for (int ni = 0; ni < 5; ni++)
                    MMA16816(c[mi][ni], a[ks][mi], b[ks][ni]);

        if (t + 1 < G1_NT) {
            stsA((t + 1) & 1, (uint32_t)((t + 1) & 1) * SMA_BYTES);  // A(t+1)
            asm volatile("cp.async.wait_group 1;\n");                // B(t+1) ready
            __syncthreads();
        }
        if (++bB == 3) bB = 0;
    }

    // ---- epilogue -----------------------------------------------------------
#pragma unroll
    for (int mi = 0; mi < 4; mi++) {
        int r0 = m0 + mi * 16 + gid;
        int r1 = r0 + 8;
#pragma unroll
        for (int ni = 0; ni < 5; ni++) {
            int col = wn * 40 + ni * 8 + 2 * tig;
            if (r0 < N_NODES)
                *reinterpret_cast<float2*>(g_H1 + (size_t)r0 * HID + col) =
                    make_float2(c[mi][ni][0], c[mi][ni][1]);
            if (r1 < N_NODES)
                *reinterpret_cast<float2*>(g_H1 + (size_t)r1 * HID + col) =
                    make_float2(c[mi][ni][2], c[mi][ni][3]);
        }
    }
}

// ---------------- degree accumulate ------------------------------------------
__global__ void accum_kernel(const void* __restrict__ ei,
                             const float* __restrict__ ew) {
    int e = blockIdx.x * blockDim.x + threadIdx.x;
    if (e >= N_EDGES) return;
    int is64 = g_is64;
    int d = edge_at(ei, (size_t)N_EDGES + e, is64);
    atomicAdd(&g_dis[d], ew[e]);
    atomicAdd(&g_cnt[d], 1);
}

__global__ void rsqrt_kernel() {
    int i = blockIdx.x * blockDim.x + threadIdx.x;
    if (i < N_NODES) {
        float dg = g_dis[i];
        g_dis[i] = (dg > 0.0f) ? rsqrtf(dg) : 0.0f;
    }
}

// ---------------- exclusive scan (single block) ------------------------------
__global__ void scan_kernel() {
    __shared__ int part[1024];
    const int tid = threadIdx.x;
    const int CH = (N_NODES + 1023) / 1024;
    int base = tid * CH;
    int s = 0;
    for (int i = 0; i < CH; i++) {
        int idx = base + i;
        if (idx < N_NODES) s += g_cnt[idx];
    }
    part[tid] = s;
    __syncthreads();
    for (int off = 1; off < 1024; off <<= 1) {
        int v = (tid >= off) ? part[tid - off] : 0;
        __syncthreads();
        part[tid] += v;
        __syncthreads();
    }
    int ex = part[tid] - s;
    for (int i = 0; i < CH; i++) {
        int idx = base + i;
        if (idx < N_NODES) {
            g_off[idx] = ex;
            g_cur[idx] = ex;
            ex += g_cnt[idx];
        }
    }
    if (tid == 1023) g_off[N_NODES] = part[1023];
}

// ---------------- CSR fill ----------------------------------------------------
__global__ void fill_kernel(const void* __restrict__ ei,
                            const float* __restrict__ ew) {
    int e = blockIdx.x * blockDim.x + threadIdx.x;
    if (e >= N_EDGES) return;
    int is64 = g_is64;
    int s = edge_at(ei, e, is64);
    int d = edge_at(ei, (size_t)N_EDGES + e, is64);
    float w = g_dis[s] * ew[e] * g_dis[d];
    int pos = atomicAdd(&g_cur[d], 1);
    g_csr_src[pos] = s;
    g_csr_w[pos] = w;
}

// ---------------- propagation 1: CSR gather + bias + relu --------------------
__global__ __launch_bounds__(224)
void prop1_kernel(const float* __restrict__ b1) {
    const int n = blockIdx.x;
    const int col = threadIdx.x;
    if (col >= HID) return;
    float dv = g_dis[n];
    float acc = g_H1[(size_t)n * HID + col] * (dv * dv);
    int e = g_off[n], end = g_off[n + 1];
    for (; e + 4 <= end; e += 4) {
        int s0 = g_csr_src[e],     s1 = g_csr_src[e + 1];
        int s2 = g_csr_src[e + 2], s3 = g_csr_src[e + 3];
        float w0 = g_csr_w[e],     w1 = g_csr_w[e + 1];
        float w2 = g_csr_w[e + 2], w3 = g_csr_w[e + 3];
        float x0 = g_H1[(size_t)s0 * HID + col];
        float x1 = g_H1[(size_t)s1 * HID + col];
        float x2 = g_H1[(size_t)s2 * HID + col];
        float x3 = g_H1[(size_t)s3 * HID + col];
        acc += x0 * w0 + x1 * w1 + x2 * w2 + x3 * w3;
    }
    for (; e < end; e++)
        acc += g_H1[(size_t)g_csr_src[e] * HID + col] * g_csr_w[e];
    float v = acc + b1[col];
    g_h[(size_t)n * HID + col] = v > 0.f ? v : 0.f;
}

// ---------------- GEMM2 -------------------------------------------------------
__global__ void gemm2_kernel(const float* __restrict__ W2) {
    __shared__ float W2s[HID * OUT_DIM];
    int tid = threadIdx.x;
    for (int i = tid; i < HID * OUT_DIM; i += blockDim.x) W2s[i] = W2[i];
    __syncthreads();
    int row = blockIdx.x * blockDim.x + tid;
    if (row >= N_NODES) return;
    float acc[OUT_DIM];
#pragma unroll
    for (int o = 0; o < OUT_DIM; o++) acc[o] = 0.f;
    const float4* hq = reinterpret_cast<const float4*>(g_h + (size_t)row * HID);
#pragma unroll 5
    for (int q = 0; q < HID / 4; q++) {
        float4 v = hq[q];
        float hv[4] = {v.x, v.y, v.z, v.w};
#pragma unroll
        for (int j = 0; j < 4; j++) {
            int k = q * 4 + j;
#pragma unroll
            for (int o = 0; o < OUT_DIM; o++) acc[o] += hv[j] * W2s[k * OUT_DIM + o];
        }
    }
#pragma unroll
    for (int o = 0; o < OUT_DIM; o++)
        g_H2[(size_t)row * OUT_DIM + o] = acc[o];
}

// ---------------- propagation 2 ----------------------------------------------
__global__ void prop2_kernel(const float* __restrict__ b2,
                             float* __restrict__ outp) {
    int n = blockIdx.x * 4 + (threadIdx.x >> 5);
    if (n >= N_NODES) return;
    int lane = threadIdx.x & 31;
    int sub = lane >> 3;
    int col = lane & 7;
    float acc = 0.f;
    int beg = g_off[n], end = g_off[n + 1];
    for (int e = beg + sub; e < end; e += 4)
        acc += g_H2[(size_t)g_csr_src[e] * OUT_DIM + col] * g_csr_w[e];
    acc += __shfl_xor_sync(0xffffffffu, acc, 8);
    acc += __shfl_xor_sync(0xffffffffu, acc, 16);
    if (sub == 0) {
        float dv = g_dis[n];
        outp[(size_t)n * OUT_DIM + col] =
            acc + g_H2[(size_t)n * OUT_DIM + col] * (dv * dv) + b2[col];
    }
}

// ---------------- launch -----------------------------------------------------
extern "C" void kernel_launch(void* const* d_in, const int* in_sizes, int n_in,
                              void* d_out, int out_size) {
    const float* x  = (const float*)d_in[0];
    const float* ew = (const float*)d_in[1];
    const float* W1 = (const float*)d_in[2];
    const float* b1 = (const float*)d_in[3];
    const float* W2 = (const float*)d_in[4];
    const float* b2 = (const float*)d_in[5];
    const void*  ei = d_in[6];
    float* outp = (float*)d_out;

    static cudaStream_t s1 = nullptr;
    static cudaEvent_t evFork = nullptr, evJoin = nullptr;
    if (!s1) {
        cudaStreamCreateWithFlags(&s1, cudaStreamNonBlocking);
        cudaEventCreateWithFlags(&evFork, cudaEventDisableTiming);
        cudaEventCreateWithFlags(&evJoin, cudaEventDisableTiming);
    }

    cudaEventRecord(evFork, 0);
    cudaStreamWaitEvent(s1, evFork, 0);

    detect_kernel<<<1, 256, 0, s1>>>((const unsigned*)ei, 4096);
    init_kernel<<<(N_NODES + 255) / 256, 256, 0, s1>>>();
    w1t_kernel<<<dim3((HID + 31) / 32, (IN_DIM + 31) / 32), dim3(32, 8)>>>(W1);
    gemm1_kernel<<<(N_NODES + G1_BM - 1) / G1_BM, G1T>>>(x);
    accum_kernel<<<(N_EDGES + 255) / 256, 256, 0, s1>>>(ei, ew);
    rsqrt_kernel<<<(N_NODES + 255) / 256, 256, 0, s1>>>();
    scan_kernel<<<1, 1024, 0, s1>>>();
    fill_kernel<<<(N_EDGES + 255) / 256, 256, 0, s1>>>(ei, ew);

    cudaEventRecord(evJoin, s1);
    cudaStreamWaitEvent(0, evJoin, 0);

    prop1_kernel<<<N_NODES, 224>>>(b1);
    gemm2_kernel<<<(N_NODES + 255) / 256, 256>>>(W2);
    prop2_kernel<<<(N_NODES + 3) / 4, 128>>>(b2, outp);
}

// round 10
// speedup vs baseline: 1.4358x; 1.4358x over previous
#include <cuda_runtime.h>
#include <cuda_fp16.h>
#include <cstdint>

#define N_NODES 50000
#define IN_DIM  7688
#define HID     200
#define OUT_DIM 8
#define N_EDGES 1600000

// ---------------- scratch (device globals; no allocation allowed) -------------
__device__ float  g_dis[N_NODES];
__device__ int    g_cnt[N_NODES];
__device__ int    g_off[N_NODES + 1];
__device__ int    g_cur[N_NODES];
__device__ int    g_csr_src[N_EDGES];
__device__ float  g_csr_w[N_EDGES];
__device__ __half g_W1h[(size_t)HID * IN_DIM];      // W1^T in fp16, [n][k]
__device__ float  g_H1[(size_t)N_NODES * HID];
__device__ float  g_h[(size_t)N_NODES * HID];
__device__ float  g_H2[(size_t)N_NODES * OUT_DIM];
__device__ int    g_is64;

// ---------------- helpers ----------------------------------------------------
__device__ __forceinline__ int edge_at(const void* ei, size_t pos, int is64) {
    if (is64) return (int)((const long long*)ei)[pos];
    return ((const int*)ei)[pos];
}

__device__ __forceinline__ uint32_t smem_u32(const void* p) {
    uint32_t a;
    asm("{ .reg .u64 t; cvta.to.shared.u64 t, %1; cvt.u32.u64 %0, t; }"
        : "=r"(a) : "l"(p));
    return a;
}

__device__ __forceinline__ void cp16(uint32_t saddr, const void* g, int sz) {
    asm volatile("cp.async.cg.shared.global [%0], [%1], 16, %2;\n"
                 :: "r"(saddr), "l"(g), "r"(sz));
}

#define LDSM4(r0, r1, r2, r3, a)                                               \
    asm volatile("ldmatrix.sync.aligned.m8n8.x4.shared.b16 {%0,%1,%2,%3},[%4];"\
                 : "=r"(r0), "=r"(r1), "=r"(r2), "=r"(r3) : "r"(a))

#define LDSM2(r0, r1, a)                                                       \
    asm volatile("ldmatrix.sync.aligned.m8n8.x2.shared.b16 {%0,%1},[%2];"      \
                 : "=r"(r0), "=r"(r1) : "r"(a))

#define MMA16816(c, a, b)                                                      \
    asm volatile(                                                              \
        "mma.sync.aligned.m16n8k16.row.col.f32.f16.f16.f32 "                   \
        "{%0,%1,%2,%3},{%4,%5,%6,%7},{%8,%9},{%0,%1,%2,%3};\n"                 \
        : "+f"((c)[0]), "+f"((c)[1]), "+f"((c)[2]), "+f"((c)[3])               \
        : "r"((a)[0]), "r"((a)[1]), "r"((a)[2]), "r"((a)[3]),                  \
          "r"((b)[0]), "r"((b)[1]))

// ---------------- dtype detection --------------------------------------------
__global__ void detect_kernel(const unsigned* __restrict__ w, int n_check) {
    __shared__ int bad;
    if (threadIdx.x == 0) bad = 0;
    __syncthreads();
    int local = 0;
    for (int i = threadIdx.x; i < n_check; i += blockDim.x)
        if (w[2 * i + 1] != 0u) local = 1;
    if (local) bad = 1;
    __syncthreads();
    if (threadIdx.x == 0) g_is64 = bad ? 0 : 1;
}

// ---------------- degree + histogram init ------------------------------------
__global__ void init_kernel() {
    int i = blockIdx.x * blockDim.x + threadIdx.x;
    if (i < N_NODES) { g_dis[i] = 1.0f; g_cnt[i] = 0; }
}

// ---------------- W1 transpose + fp16 convert --------------------------------
__global__ void w1t_kernel(const float* __restrict__ W1) {
    __shared__ float tile[32][33];
    int kb = blockIdx.y * 32, nb = blockIdx.x * 32;
    for (int j = threadIdx.y; j < 32; j += 8) {
        int k = kb + j, n = nb + threadIdx.x;
        tile[j][threadIdx.x] =
            (k < IN_DIM && n < HID) ? W1[(size_t)k * HID + n] : 0.f;
    }
    __syncthreads();
    for (int j = threadIdx.y; j < 32; j += 8) {
        int n = nb + j, k = kb + threadIdx.x;
        if (n < HID && k < IN_DIM)
            g_W1h[(size_t)n * IN_DIM + k] = __float2half_rn(tile[threadIdx.x][j]);
    }
}

// ---------------- GEMM1: 64x200 CTA, BK=64, fp16 HMMA ------------------------
#define G1T   160
#define G1_BM 64
#define G1_BK 64
#define G1_NT 121                 // ceil(7688/64)
#define SMA_BYTES (G1_BM * 128)   // 8192 per buffer
#define SMB_BYTES (200 * 128)     // 25600 per buffer
#define G1_SMEM (2 * SMA_BYTES + 2 * SMB_BYTES)   // 67584

__global__ __launch_bounds__(G1T, 2)
void gemm1_kernel(const float* __restrict__ X) {
    extern __shared__ __align__(16) unsigned char smem[];
    unsigned char* smA = smem;                       // 2 x SMA_BYTES
    unsigned char* smB = smem + 2 * SMA_BYTES;       // 2 x SMB_BYTES
    const uint32_t smA0 = smem_u32(smA);
    const uint32_t smB0 = smem_u32(smB);

    const int tid  = threadIdx.x;
    const int lane = tid & 31;
    const int warp = tid >> 5;          // 0..4 = n-slot
    const int gid  = lane >> 2;
    const int tig  = lane & 3;
    const int wn   = warp;
    const int m0   = blockIdx.x * G1_BM;

    // ---- A fill: 64 rows x 8 chunks(16B fp16 = 8 k) = 512 chunks ------------
    // thread handles chunks idx = tid + j*160, j=0..3 (idx<512)
    int   aR[4], aC[4];
    uint32_t aDst[4];
    bool  aOkRow[4], aHas[4];
    const float* aSrc[4];
#pragma unroll
    for (int j = 0; j < 4; j++) {
        int idx = tid + j * G1T;
        aHas[j] = idx < 512;
        int r = (idx < 512) ? (idx >> 3) : 0;
        int c = idx & 7;
        aR[j] = r; aC[j] = c;
        aDst[j] = (uint32_t)(r * 128 + ((c ^ (r & 7)) << 4));
        aOkRow[j] = aHas[j] && ((m0 + r) < N_NODES);
        aSrc[j] = X + (size_t)(aOkRow[j] ? (m0 + r) : 0) * IN_DIM + c * 8;
    }

    float4 va[4][2];
    auto ldgA = [&](int k0) {
        const float4 z = make_float4(0.f, 0.f, 0.f, 0.f);
#pragma unroll
        for (int j = 0; j < 4; j++) {
            bool ok = aOkRow[j] && ((k0 + aC[j] * 8 + 8) <= IN_DIM);
            if (ok) {
                va[j][0] = *reinterpret_cast<const float4*>(aSrc[j] + k0);
                va[j][1] = *reinterpret_cast<const float4*>(aSrc[j] + k0 + 4);
            } else { va[j][0] = z; va[j][1] = z; }
        }
    };
    auto stsA = [&](int buf) {
        unsigned char* base = smA + buf * SMA_BYTES;
#pragma unroll
        for (int j = 0; j < 4; j++) {
            if (!aHas[j]) continue;
            __half2 h0 = __floats2half2_rn(va[j][0].x, va[j][0].y);
            __half2 h1 = __floats2half2_rn(va[j][0].z, va[j][0].w);
            __half2 h2 = __floats2half2_rn(va[j][1].x, va[j][1].y);
            __half2 h3 = __floats2half2_rn(va[j][1].z, va[j][1].w);
            *reinterpret_cast<uint4*>(base + aDst[j]) =
                make_uint4(*(uint32_t*)&h0, *(uint32_t*)&h1,
                           *(uint32_t*)&h2, *(uint32_t*)&h3);
        }
    };
    // ---- B fill: 200 rows x 8 chunks = 1600 chunks = 10 per thread ----------
    auto cpB = [&](int k0, int buf) {
        const uint32_t bb = smB0 + (uint32_t)buf * SMB_BYTES;
#pragma unroll
        for (int j = 0; j < 10; j++) {
            int idx = tid + j * G1T;
            int n = idx >> 3, c = idx & 7;
            int ok = (k0 + c * 8 + 8) <= IN_DIM;
            const __half* src = g_W1h + (size_t)n * IN_DIM + (ok ? (k0 + c * 8) : 0);
            cp16(bb + (uint32_t)(n * 128 + ((c ^ (n & 7)) << 4)), src, ok ? 16 : 0);
        }
        asm volatile("cp.async.commit_group;\n");
    };

    // ---- fragment offsets ----------------------------------------------------
    uint32_t aRow[4], bCol[5];
#pragma unroll
    for (int mi = 0; mi < 4; mi++)
        aRow[mi] = (uint32_t)((mi * 16 + (lane & 15)) * 128);
#pragma unroll
    for (int ni = 0; ni < 5; ni++)
        bCol[ni] = (uint32_t)((wn * 40 + ni * 8 + (lane & 7)) * 128);
    const int xorA = lane & 7;          // row&7 for A frag rows (mi*16 multiple of 8)
    const int khalfA = lane >> 4;       // 0/1
    const int xorB = lane & 7;          // row&7 for B frag rows
    const int bhalfB = (lane >> 3) & 1;

    float c[4][5][4];
#pragma unroll
    for (int mi = 0; mi < 4; mi++)
#pragma unroll
        for (int ni = 0; ni < 5; ni++)
#pragma unroll
            for (int r = 0; r < 4; r++) c[mi][ni][r] = 0.0f;

    // ---- prologue ------------------------------------------------------------
    ldgA(0);
    cpB(0, 0);
    stsA(0);
    asm volatile("cp.async.wait_group 0;\n");
    __syncthreads();

    // ---- main loop: 121 iters, 4 k-steps each --------------------------------
    for (int t = 0; t < G1_NT; t++) {
        const int buf = t & 1;
        const bool more = (t + 1) < G1_NT;
        if (more) {
            ldgA((t + 1) * G1_BK);
            cpB((t + 1) * G1_BK, buf ^ 1);
        }
        const uint32_t ab = smA0 + (uint32_t)buf * SMA_BYTES;
        const uint32_t bb = smB0 + (uint32_t)buf * SMB_BYTES;

        uint32_t a[2][4][4], b[2][5][2];
        auto loadF = [&](int ks, int set) {
            uint32_t aoff = (uint32_t)(((ks * 2 + khalfA) ^ xorA) << 4);
            uint32_t boff = (uint32_t)(((ks * 2 + bhalfB) ^ xorB) << 4);
#pragma unroll
            for (int mi = 0; mi < 4; mi++)
                LDSM4(a[set][mi][0], a[set][mi][1], a[set][mi][2], a[set][mi][3],
                      ab + aRow[mi] + aoff);
#pragma unroll
            for (int ni = 0; ni < 5; ni++)
                LDSM2(b[set][ni][0], b[set][ni][1], bb + bCol[ni] + boff);
        };
        loadF(0, 0);
#pragma unroll
        for (int ks = 0; ks < 4; ks++) {
            const int cur = ks & 1;
            if (ks < 3) loadF(ks + 1, cur ^ 1);
#pragma unroll
            for (int mi = 0; mi < 4; mi++)
#pragma unroll
                for (int ni = 0; ni < 5; ni++)
                    MMA16816(c[mi][ni], a[cur][mi], b[cur][ni]);
        }

        if (more) {
            stsA(buf ^ 1);
            asm volatile("cp.async.wait_group 0;\n");
        }
        __syncthreads();
    }

    // ---- epilogue -----------------------------------------------------------
#pragma unroll
    for (int mi = 0; mi < 4; mi++) {
        int r0 = m0 + mi * 16 + gid;
        int r1 = r0 + 8;
#pragma unroll
        for (int ni = 0; ni < 5; ni++) {
            int col = wn * 40 + ni * 8 + 2 * tig;
            if (r0 < N_NODES)
                *reinterpret_cast<float2*>(g_H1 + (size_t)r0 * HID + col) =
                    make_float2(c[mi][ni][0], c[mi][ni][1]);
            if (r1 < N_NODES)
                *reinterpret_cast<float2*>(g_H1 + (size_t)r1 * HID + col) =
                    make_float2(c[mi][ni][2], c[mi][ni][3]);
        }
    }
}

// ---------------- degree accumulate ------------------------------------------
__global__ void accum_kernel(const void* __restrict__ ei,
                             const float* __restrict__ ew) {
    int e = blockIdx.x * blockDim.x + threadIdx.x;
    if (e >= N_EDGES) return;
    int is64 = g_is64;
    int d = edge_at(ei, (size_t)N_EDGES + e, is64);
    atomicAdd(&g_dis[d], ew[e]);
    atomicAdd(&g_cnt[d], 1);
}

__global__ void rsqrt_kernel() {
    int i = blockIdx.x * blockDim.x + threadIdx.x;
    if (i < N_NODES) {
        float dg = g_dis[i];
        g_dis[i] = (dg > 0.0f) ? rsqrtf(dg) : 0.0f;
    }
}

// ---------------- exclusive scan (single block) ------------------------------
__global__ void scan_kernel() {
    __shared__ int part[1024];
    const int tid = threadIdx.x;
    const int CH = (N_NODES + 1023) / 1024;
    int base = tid * CH;
    int s = 0;
    for (int i = 0; i < CH; i++) {
        int idx = base + i;
        if (idx < N_NODES) s += g_cnt[idx];
    }
    part[tid] = s;
    __syncthreads();
    for (int off = 1; off < 1024; off <<= 1) {
        int v = (tid >= off) ? part[tid - off] : 0;
        __syncthreads();
        part[tid] += v;
        __syncthreads();
    }
    int ex = part[tid] - s;
    for (int i = 0; i < CH; i++) {
        int idx = base + i;
        if (idx < N_NODES) {
            g_off[idx] = ex;
            g_cur[idx] = ex;
            ex += g_cnt[idx];
        }
    }
    if (tid == 1023) g_off[N_NODES] = part[1023];
}

// ---------------- CSR fill ----------------------------------------------------
__global__ void fill_kernel(const void* __restrict__ ei,
                            const float* __restrict__ ew) {
    int e = blockIdx.x * blockDim.x + threadIdx.x;
    if (e >= N_EDGES) return;
    int is64 = g_is64;
    int s = edge_at(ei, e, is64);
    int d = edge_at(ei, (size_t)N_EDGES + e, is64);
    float w = g_dis[s] * ew[e] * g_dis[d];
    int pos = atomicAdd(&g_cur[d], 1);
    g_csr_src[pos] = s;
    g_csr_w[pos] = w;
}

// ---------------- propagation 1: CSR gather + bias + relu --------------------
__global__ __launch_bounds__(224)
void prop1_kernel(const float* __restrict__ b1) {
    const int n = blockIdx.x;
    const int col = threadIdx.x;
    if (col >= HID) return;
    float dv = g_dis[n];
    float acc = g_H1[(size_t)n * HID + col] * (dv * dv);
    int e = g_off[n], end = g_off[n + 1];
    for (; e + 4 <= end; e += 4) {
        int s0 = g_csr_src[e],     s1 = g_csr_src[e + 1];
        int s2 = g_csr_src[e + 2], s3 = g_csr_src[e + 3];
        float w0 = g_csr_w[e],     w1 = g_csr_w[e + 1];
        float w2 = g_csr_w[e + 2], w3 = g_csr_w[e + 3];
        float x0 = g_H1[(size_t)s0 * HID + col];
        float x1 = g_H1[(size_t)s1 * HID + col];
        float x2 = g_H1[(size_t)s2 * HID + col];
        float x3 = g_H1[(size_t)s3 * HID + col];
        acc += x0 * w0 + x1 * w1 + x2 * w2 + x3 * w3;
    }
    for (; e < end; e++)
        acc += g_H1[(size_t)g_csr_src[e] * HID + col] * g_csr_w[e];
    float v = acc + b1[col];
    g_h[(size_t)n * HID + col] = v > 0.f ? v : 0.f;
}

// ---------------- GEMM2 -------------------------------------------------------
__global__ void gemm2_kernel(const float* __restrict__ W2) {
    __shared__ float W2s[HID * OUT_DIM];
    int tid = threadIdx.x;
    for (int i = tid; i < HID * OUT_DIM; i += blockDim.x) W2s[i] = W2[i];
    __syncthreads();
    int row = blockIdx.x * blockDim.x + tid;
    if (row >= N_NODES) return;
    float acc[OUT_DIM];
#pragma unroll
    for (int o = 0; o < OUT_DIM; o++) acc[o] = 0.f;
    const float4* hq = reinterpret_cast<const float4*>(g_h + (size_t)row * HID);
#pragma unroll 5
    for (int q = 0; q < HID / 4; q++) {
        float4 v = hq[q];
        float hv[4] = {v.x, v.y, v.z, v.w};
#pragma unroll
        for (int j = 0; j < 4; j++) {
            int k = q * 4 + j;
#pragma unroll
            for (int o = 0; o < OUT_DIM; o++) acc[o] += hv[j] * W2s[k * OUT_DIM + o];
        }
    }
#pragma unroll
    for (int o = 0; o < OUT_DIM; o++)
        g_H2[(size_t)row * OUT_DIM + o] = acc[o];
}

// ---------------- propagation 2 ----------------------------------------------
__global__ void prop2_kernel(const float* __restrict__ b2,
                             float* __restrict__ outp) {
    int n = blockIdx.x * 4 + (threadIdx.x >> 5);
    if (n >= N_NODES) return;
    int lane = threadIdx.x & 31;
    int sub = lane >> 3;
    int col = lane & 7;
    float acc = 0.f;
    int beg = g_off[n], end = g_off[n + 1];
    for (int e = beg + sub; e < end; e += 4)
        acc += g_H2[(size_t)g_csr_src[e] * OUT_DIM + col] * g_csr_w[e];
    acc += __shfl_xor_sync(0xffffffffu, acc, 8);
    acc += __shfl_xor_sync(0xffffffffu, acc, 16);
    if (sub == 0) {
        float dv = g_dis[n];
        outp[(size_t)n * OUT_DIM + col] =
            acc + g_H2[(size_t)n * OUT_DIM + col] * (dv * dv) + b2[col];
    }
}

// ---------------- launch -----------------------------------------------------
extern "C" void kernel_launch(void* const* d_in, const int* in_sizes, int n_in,
                              void* d_out, int out_size) {
    const float* x  = (const float*)d_in[0];
    const float* ew = (const float*)d_in[1];
    const float* W1 = (const float*)d_in[2];
    const float* b1 = (const float*)d_in[3];
    const float* W2 = (const float*)d_in[4];
    const float* b2 = (const float*)d_in[5];
    const void*  ei = d_in[6];
    float* outp = (float*)d_out;

    static cudaStream_t s1 = nullptr;
    static cudaEvent_t evFork = nullptr, evJoin = nullptr;
    if (!s1) {
        cudaStreamCreateWithFlags(&s1, cudaStreamNonBlocking);
        cudaEventCreateWithFlags(&evFork, cudaEventDisableTiming);
        cudaEventCreateWithFlags(&evJoin, cudaEventDisableTiming);
        cudaFuncSetAttribute(gemm1_kernel,
                             cudaFuncAttributeMaxDynamicSharedMemorySize, G1_SMEM);
    }

    cudaEventRecord(evFork, 0);
    cudaStreamWaitEvent(s1, evFork, 0);

    detect_kernel<<<1, 256, 0, s1>>>((const unsigned*)ei, 4096);
    init_kernel<<<(N_NODES + 255) / 256, 256, 0, s1>>>();
    w1t_kernel<<<dim3((HID + 31) / 32, (IN_DIM + 31) / 32), dim3(32, 8)>>>(W1);
    gemm1_kernel<<<(N_NODES + G1_BM - 1) / G1_BM, G1T, G1_SMEM>>>(x);
    accum_kernel<<<(N_EDGES + 255) / 256, 256, 0, s1>>>(ei, ew);
    rsqrt_kernel<<<(N_NODES + 255) / 256, 256, 0, s1>>>();
    scan_kernel<<<1, 1024, 0, s1>>>();
    fill_kernel<<<(N_EDGES + 255) / 256, 256, 0, s1>>>(ei, ew);

    cudaEventRecord(evJoin, s1);
    cudaStreamWaitEvent(0, evJoin, 0);

    prop1_kernel<<<N_NODES, 224>>>(b1);
    gemm2_kernel<<<(N_NODES + 255) / 256, 256>>>(W2);
    prop2_kernel<<<(N_NODES + 3) / 4, 128>>>(b2, outp);
}

// round 11
// speedup vs baseline: 1.7198x; 1.1978x over previous
#include <cuda_runtime.h>
#include <cuda_fp16.h>
#include <cstdint>

#define N_NODES 50000
#define IN_DIM  7688
#define HID     200
#define N_PAD   224
#define OUT_DIM 8
#define N_EDGES 1600000

// ---------------- scratch (device globals; no allocation allowed) -------------
__device__ float  g_dis[N_NODES];
__device__ int    g_cnt[N_NODES];
__device__ int    g_off[N_NODES + 1];
__device__ int    g_cur[N_NODES];
__device__ int    g_csr_src[N_EDGES];
__device__ float  g_csr_w[N_EDGES];
__device__ __half g_W1h[(size_t)N_PAD * IN_DIM];    // W1^T fp16, [n][k], rows>=200 zero
__device__ float  g_H1[(size_t)N_NODES * HID];
__device__ float  g_h[(size_t)N_NODES * HID];
__device__ float  g_H2[(size_t)N_NODES * OUT_DIM];
__device__ int    g_is64;

// ---------------- helpers ----------------------------------------------------
__device__ __forceinline__ int edge_at(const void* ei, size_t pos, int is64) {
    if (is64) return (int)((const long long*)ei)[pos];
    return ((const int*)ei)[pos];
}

__device__ __forceinline__ uint32_t smem_u32(const void* p) {
    uint32_t a;
    asm("{ .reg .u64 t; cvta.to.shared.u64 t, %1; cvt.u32.u64 %0, t; }"
        : "=r"(a) : "l"(p));
    return a;
}

__device__ __forceinline__ void cp16(uint32_t saddr, const void* g, int sz) {
    asm volatile("cp.async.cg.shared.global [%0], [%1], 16, %2;\n"
                 :: "r"(saddr), "l"(g), "r"(sz));
}

#define LDSM4(r0, r1, r2, r3, a)                                               \
    asm volatile("ldmatrix.sync.aligned.m8n8.x4.shared.b16 {%0,%1,%2,%3},[%4];"\
                 : "=r"(r0), "=r"(r1), "=r"(r2), "=r"(r3) : "r"(a))

#define LDSM2(r0, r1, a)                                                       \
    asm volatile("ldmatrix.sync.aligned.m8n8.x2.shared.b16 {%0,%1},[%2];"      \
                 : "=r"(r0), "=r"(r1) : "r"(a))

#define MMA16816(c, a, b)                                                      \
    asm volatile(                                                              \
        "mma.sync.aligned.m16n8k16.row.col.f32.f16.f16.f32 "                   \
        "{%0,%1,%2,%3},{%4,%5,%6,%7},{%8,%9},{%0,%1,%2,%3};\n"                 \
        : "+f"((c)[0]), "+f"((c)[1]), "+f"((c)[2]), "+f"((c)[3])               \
        : "r"((a)[0]), "r"((a)[1]), "r"((a)[2]), "r"((a)[3]),                  \
          "r"((b)[0]), "r"((b)[1]))

// ---------------- dtype detection --------------------------------------------
__global__ void detect_kernel(const unsigned* __restrict__ w, int n_check) {
    __shared__ int bad;
    if (threadIdx.x == 0) bad = 0;
    __syncthreads();
    int local = 0;
    for (int i = threadIdx.x; i < n_check; i += blockDim.x)
        if (w[2 * i + 1] != 0u) local = 1;
    if (local) bad = 1;
    __syncthreads();
    if (threadIdx.x == 0) g_is64 = bad ? 0 : 1;
}

// ---------------- degree + histogram init ------------------------------------
__global__ void init_kernel() {
    int i = blockIdx.x * blockDim.x + threadIdx.x;
    if (i < N_NODES) { g_dis[i] = 1.0f; g_cnt[i] = 0; }
}

// ---------------- W1 transpose + fp16 convert (padded to 224 rows) -----------
__global__ void w1t_kernel(const float* __restrict__ W1) {
    __shared__ float tile[32][33];
    int kb = blockIdx.y * 32, nb = blockIdx.x * 32;
    for (int j = threadIdx.y; j < 32; j += 8) {
        int k = kb + j, n = nb + threadIdx.x;
        tile[j][threadIdx.x] =
            (k < IN_DIM && n < HID) ? W1[(size_t)k * HID + n] : 0.f;
    }
    __syncthreads();
    for (int j = threadIdx.y; j < 32; j += 8) {
        int n = nb + j, k = kb + threadIdx.x;
        if (n < N_PAD && k < IN_DIM)
            g_W1h[(size_t)n * IN_DIM + k] = __float2half_rn(tile[threadIdx.x][j]);
    }
}

// ---------------- GEMM1: 64x224 CTA, BK=64, 4 warps, 2 CTAs/SM ---------------
#define G1T   128
#define G1_BM 64
#define G1_BK 64
#define G1_NT 121                   // ceil(7688/64)
#define SMA_BYTES (G1_BM * 128)     // 8192 per buffer
#define SMB_BYTES (N_PAD * 128)     // 28672 per buffer
#define G1_SMEM (2 * SMA_BYTES + 2 * SMB_BYTES)   // 73728

__global__ __launch_bounds__(G1T, 2)
void gemm1_kernel(const float* __restrict__ X) {
    extern __shared__ __align__(16) unsigned char smem[];
    unsigned char* smA = smem;                       // 2 x SMA_BYTES
    unsigned char* smB = smem + 2 * SMA_BYTES;       // 2 x SMB_BYTES
    const uint32_t smA0 = smem_u32(smA);
    const uint32_t smB0 = smem_u32(smB);

    const int tid  = threadIdx.x;
    const int lane = tid & 31;
    const int warp = tid >> 5;          // 0..3 = n-slot (one per SMSP)
    const int gid  = lane >> 2;
    const int tig  = lane & 3;
    const int wn   = warp;
    const int m0   = blockIdx.x * G1_BM;

    // ---- A fill: 64 rows x 8 chunks(16B) = 512 chunks = 4/thread ------------
    int aC[4];
    uint32_t aDst[4];
    bool aOkRow[4];
    const float* aSrc[4];
#pragma unroll
    for (int j = 0; j < 4; j++) {
        int idx = tid + j * G1T;
        int r = idx >> 3, c = idx & 7;
        aC[j] = c;
        aDst[j] = (uint32_t)(r * 128 + ((c ^ (r & 7)) << 4));
        aOkRow[j] = (m0 + r) < N_NODES;
        aSrc[j] = X + (size_t)(aOkRow[j] ? (m0 + r) : 0) * IN_DIM + c * 8;
    }

    float4 va[4][2];
    auto ldgA = [&](int k0) {
        const float4 z = make_float4(0.f, 0.f, 0.f, 0.f);
#pragma unroll
        for (int j = 0; j < 4; j++) {
            bool ok = aOkRow[j] && ((k0 + aC[j] * 8 + 8) <= IN_DIM);
            if (ok) {
                va[j][0] = *reinterpret_cast<const float4*>(aSrc[j] + k0);
                va[j][1] = *reinterpret_cast<const float4*>(aSrc[j] + k0 + 4);
            } else { va[j][0] = z; va[j][1] = z; }
        }
    };
    auto stsA = [&](int buf) {
        unsigned char* base = smA + buf * SMA_BYTES;
#pragma unroll
        for (int j = 0; j < 4; j++) {
            __half2 h0 = __floats2half2_rn(va[j][0].x, va[j][0].y);
            __half2 h1 = __floats2half2_rn(va[j][0].z, va[j][0].w);
            __half2 h2 = __floats2half2_rn(va[j][1].x, va[j][1].y);
            __half2 h3 = __floats2half2_rn(va[j][1].z, va[j][1].w);
            *reinterpret_cast<uint4*>(base + aDst[j]) =
                make_uint4(*(uint32_t*)&h0, *(uint32_t*)&h1,
                           *(uint32_t*)&h2, *(uint32_t*)&h3);
        }
    };
    // ---- B fill: 224 rows x 8 chunks = 1792 chunks = 14/thread --------------
    auto cpB = [&](int k0, int buf) {
        const uint32_t bb = smB0 + (uint32_t)buf * SMB_BYTES;
#pragma unroll
        for (int j = 0; j < 14; j++) {
            int idx = tid + j * G1T;
            int n = idx >> 3, c = idx & 7;
            int ok = (k0 + c * 8 + 8) <= IN_DIM;
            const __half* src = g_W1h + (size_t)n * IN_DIM + (ok ? (k0 + c * 8) : 0);
            cp16(bb + (uint32_t)(n * 128 + ((c ^ (n & 7)) << 4)), src, ok ? 16 : 0);
        }
        asm volatile("cp.async.commit_group;\n");
    };

    // ---- fragment offsets ----------------------------------------------------
    uint32_t aRow[4], bCol[7];
#pragma unroll
    for (int mi = 0; mi < 4; mi++)
        aRow[mi] = (uint32_t)((mi * 16 + (lane & 15)) * 128);
#pragma unroll
    for (int ni = 0; ni < 7; ni++)
        bCol[ni] = (uint32_t)((wn * 56 + ni * 8 + (lane & 7)) * 128);
    const int xorA = lane & 7;
    const int khalfA = lane >> 4;
    const int xorB = lane & 7;
    const int bhalfB = (lane >> 3) & 1;

    float c[4][7][4];
#pragma unroll
    for (int mi = 0; mi < 4; mi++)
#pragma unroll
        for (int ni = 0; ni < 7; ni++)
#pragma unroll
            for (int r = 0; r < 4; r++) c[mi][ni][r] = 0.0f;

    // ---- prologue ------------------------------------------------------------
    ldgA(0);
    cpB(0, 0);
    stsA(0);
    asm volatile("cp.async.wait_group 0;\n");
    __syncthreads();

    // ---- main loop: 121 iters, 4 k-steps each --------------------------------
    for (int t = 0; t < G1_NT; t++) {
        const int buf = t & 1;
        const bool more = (t + 1) < G1_NT;
        if (more) {
            ldgA((t + 1) * G1_BK);
            cpB((t + 1) * G1_BK, buf ^ 1);
        }
        const uint32_t ab = smA0 + (uint32_t)buf * SMA_BYTES;
        const uint32_t bb = smB0 + (uint32_t)buf * SMB_BYTES;

        uint32_t a[2][4][4], b[2][7][2];
        auto loadF = [&](int ks, int set) {
            uint32_t aoff = (uint32_t)(((ks * 2 + khalfA) ^ xorA) << 4);
            uint32_t boff = (uint32_t)(((ks * 2 + bhalfB) ^ xorB) << 4);
#pragma unroll
            for (int mi = 0; mi < 4; mi++)
                LDSM4(a[set][mi][0], a[set][mi][1], a[set][mi][2], a[set][mi][3],
                      ab + aRow[mi] + aoff);
#pragma unroll
            for (int ni = 0; ni < 7; ni++)
                LDSM2(b[set][ni][0], b[set][ni][1], bb + bCol[ni] + boff);
        };
        loadF(0, 0);
#pragma unroll
        for (int ks = 0; ks < 4; ks++) {
            const int cur = ks & 1;
            if (ks < 3) loadF(ks + 1, cur ^ 1);
#pragma unroll
            for (int mi = 0; mi < 4; mi++)
#pragma unroll
                for (int ni = 0; ni < 7; ni++)
                    MMA16816(c[mi][ni], a[cur][mi], b[cur][ni]);
        }

        if (more) {
            stsA(buf ^ 1);
            asm volatile("cp.async.wait_group 0;\n");
        }
        __syncthreads();
    }

    // ---- epilogue (mask padded cols >= 200) ----------------------------------
#pragma unroll
    for (int mi = 0; mi < 4; mi++) {
        int r0 = m0 + mi * 16 + gid;
        int r1 = r0 + 8;
#pragma unroll
        for (int ni = 0; ni < 7; ni++) {
            int col = wn * 56 + ni * 8 + 2 * tig;
            if (col >= HID) continue;
            if (r0 < N_NODES)
                *reinterpret_cast<float2*>(g_H1 + (size_t)r0 * HID + col) =
                    make_float2(c[mi][ni][0], c[mi][ni][1]);
            if (r1 < N_NODES)
                *reinterpret_cast<float2*>(g_H1 + (size_t)r1 * HID + col) =
                    make_float2(c[mi][ni][2], c[mi][ni][3]);
        }
    }
}

// ---------------- degree accumulate ------------------------------------------
__global__ void accum_kernel(const void* __restrict__ ei,
                             const float* __restrict__ ew) {
    int e = blockIdx.x * blockDim.x + threadIdx.x;
    if (e >= N_EDGES) return;
    int is64 = g_is64;
    int d = edge_at(ei, (size_t)N_EDGES + e, is64);
    atomicAdd(&g_dis[d], ew[e]);
    atomicAdd(&g_cnt[d], 1);
}

__global__ void rsqrt_kernel() {
    int i = blockIdx.x * blockDim.x + threadIdx.x;
    if (i < N_NODES) {
        float dg = g_dis[i];
        g_dis[i] = (dg > 0.0f) ? rsqrtf(dg) : 0.0f;
    }
}

// ---------------- exclusive scan (single block) ------------------------------
__global__ void scan_kernel() {
    __shared__ int part[1024];
    const int tid = threadIdx.x;
    const int CH = (N_NODES + 1023) / 1024;
    int base = tid * CH;
    int s = 0;
    for (int i = 0; i < CH; i++) {
        int idx = base + i;
        if (idx < N_NODES) s += g_cnt[idx];
    }
    part[tid] = s;
    __syncthreads();
    for (int off = 1; off < 1024; off <<= 1) {
        int v = (tid >= off) ? part[tid - off] : 0;
        __syncthreads();
        part[tid] += v;
        __syncthreads();
    }
    int ex = part[tid] - s;
    for (int i = 0; i < CH; i++) {
        int idx = base + i;
        if (idx < N_NODES) {
            g_off[idx] = ex;
            g_cur[idx] = ex;
            ex += g_cnt[idx];
        }
    }
    if (tid == 1023) g_off[N_NODES] = part[1023];
}

// ---------------- CSR fill ----------------------------------------------------
__global__ void fill_kernel(const void* __restrict__ ei,
                            const float* __restrict__ ew) {
    int e = blockIdx.x * blockDim.x + threadIdx.x;
    if (e >= N_EDGES) return;
    int is64 = g_is64;
    int s = edge_at(ei, e, is64);
    int d = edge_at(ei, (size_t)N_EDGES + e, is64);
    float w = g_dis[s] * ew[e] * g_dis[d];
    int pos = atomicAdd(&g_cur[d], 1);
    g_csr_src[pos] = s;
    g_csr_w[pos] = w;
}

// ---------------- propagation 1: CSR gather + bias + relu --------------------
__global__ __launch_bounds__(224)
void prop1_kernel(const float* __restrict__ b1) {
    const int n = blockIdx.x;
    const int col = threadIdx.x;
    if (col >= HID) return;
    float dv = g_dis[n];
    float acc = g_H1[(size_t)n * HID + col] * (dv * dv);
    int e = g_off[n], end = g_off[n + 1];
    for (; e + 4 <= end; e += 4) {
        int s0 = g_csr_src[e],     s1 = g_csr_src[e + 1];
        int s2 = g_csr_src[e + 2], s3 = g_csr_src[e + 3];
        float w0 = g_csr_w[e],     w1 = g_csr_w[e + 1];
        float w2 = g_csr_w[e + 2], w3 = g_csr_w[e + 3];
        float x0 = g_H1[(size_t)s0 * HID + col];
        float x1 = g_H1[(size_t)s1 * HID + col];
        float x2 = g_H1[(size_t)s2 * HID + col];
        float x3 = g_H1[(size_t)s3 * HID + col];
        acc += x0 * w0 + x1 * w1 + x2 * w2 + x3 * w3;
    }
    for (; e < end; e++)
        acc += g_H1[(size_t)g_csr_src[e] * HID + col] * g_csr_w[e];
    float v = acc + b1[col];
    g_h[(size_t)n * HID + col] = v > 0.f ? v : 0.f;
}

// ---------------- GEMM2 -------------------------------------------------------
__global__ void gemm2_kernel(const float* __restrict__ W2) {
    __shared__ float W2s[HID * OUT_DIM];
    int tid = threadIdx.x;
    for (int i = tid; i < HID * OUT_DIM; i += blockDim.x) W2s[i] = W2[i];
    __syncthreads();
    int row = blockIdx.x * blockDim.x + tid;
    if (row >= N_NODES) return;
    float acc[OUT_DIM];
#pragma unroll
    for (int o = 0; o < OUT_DIM; o++) acc[o] = 0.f;
    const float4* hq = reinterpret_cast<const float4*>(g_h + (size_t)row * HID);
#pragma unroll 5
    for (int q = 0; q < HID / 4; q++) {
        float4 v = hq[q];
        float hv[4] = {v.x, v.y, v.z, v.w};
#pragma unroll
        for (int j = 0; j < 4; j++) {
            int k = q * 4 + j;
#pragma unroll
            for (int o = 0; o < OUT_DIM; o++) acc[o] += hv[j] * W2s[k * OUT_DIM + o];
        }
    }
#pragma unroll
    for (int o = 0; o < OUT_DIM; o++)
        g_H2[(size_t)row * OUT_DIM + o] = acc[o];
}

// ---------------- propagation 2 ----------------------------------------------
__global__ void prop2_kernel(const float* __restrict__ b2,
                             float* __restrict__ outp) {
    int n = blockIdx.x * 4 + (threadIdx.x >> 5);
    if (n >= N_NODES) return;
    int lane = threadIdx.x & 31;
    int sub = lane >> 3;
    int col = lane & 7;
    float acc = 0.f;
    int beg = g_off[n], end = g_off[n + 1];
    for (int e = beg + sub; e < end; e += 4)
        acc += g_H2[(size_t)g_csr_src[e] * OUT_DIM + col] * g_csr_w[e];
    acc += __shfl_xor_sync(0xffffffffu, acc, 8);
    acc += __shfl_xor_sync(0xffffffffu, acc, 16);
    if (sub == 0) {
        float dv = g_dis[n];
        outp[(size_t)n * OUT_DIM + col] =
            acc + g_H2[(size_t)n * OUT_DIM + col] * (dv * dv) + b2[col];
    }
}

// ---------------- launch -----------------------------------------------------
extern "C" void kernel_launch(void* const* d_in, const int* in_sizes, int n_in,
                              void* d_out, int out_size) {
    const float* x  = (const float*)d_in[0];
    const float* ew = (const float*)d_in[1];
    const float* W1 = (const float*)d_in[2];
    const float* b1 = (const float*)d_in[3];
    const float* W2 = (const float*)d_in[4];
    const float* b2 = (const float*)d_in[5];
    const void*  ei = d_in[6];
    float* outp = (float*)d_out;

    static cudaStream_t s1 = nullptr;
    static cudaEvent_t evFork = nullptr, evJoin = nullptr;
    if (!s1) {
        cudaStreamCreateWithFlags(&s1, cudaStreamNonBlocking);
        cudaEventCreateWithFlags(&evFork, cudaEventDisableTiming);
        cudaEventCreateWithFlags(&evJoin, cudaEventDisableTiming);
        cudaFuncSetAttribute(gemm1_kernel,
                             cudaFuncAttributeMaxDynamicSharedMemorySize, G1_SMEM);
    }

    cudaEventRecord(evFork, 0);
    cudaStreamWaitEvent(s1, evFork, 0);

    detect_kernel<<<1, 256, 0, s1>>>((const unsigned*)ei, 4096);
    init_kernel<<<(N_NODES + 255) / 256, 256, 0, s1>>>();
    w1t_kernel<<<dim3((N_PAD + 31) / 32, (IN_DIM + 31) / 32), dim3(32, 8)>>>(W1);
    gemm1_kernel<<<(N_NODES + G1_BM - 1) / G1_BM, G1T, G1_SMEM>>>(x);
    accum_kernel<<<(N_EDGES + 255) / 256, 256, 0, s1>>>(ei, ew);
    rsqrt_kernel<<<(N_NODES + 255) / 256, 256, 0, s1>>>();
    scan_kernel<<<1, 1024, 0, s1>>>();
    fill_kernel<<<(N_EDGES + 255) / 256, 256, 0, s1>>>(ei, ew);

    cudaEventRecord(evJoin, s1);
    cudaStreamWaitEvent(0, evJoin, 0);

    prop1_kernel<<<N_NODES, 224>>>(b1);
    gemm2_kernel<<<(N_NODES + 255) / 256, 256>>>(W2);
    prop2_kernel<<<(N_NODES + 3) / 4, 128>>>(b2, outp);
}

// round 12
// speedup vs baseline: 1.8064x; 1.0504x over previous
#include <cuda_runtime.h>
#include <cuda_fp16.h>
#include <cstdint>

#define N_NODES 50000
#define IN_DIM  7688
#define HID     200
#define N_PAD   224
#define OUT_DIM 8
#define N_EDGES 1600000

// ---------------- scratch (device globals; no allocation allowed) -------------
__device__ float  g_dis[N_NODES];
__device__ int    g_cnt[N_NODES];
__device__ int    g_off[N_NODES + 1];
__device__ int    g_cur[N_NODES];
__device__ int    g_csr_src[N_EDGES];
__device__ float  g_csr_w[N_EDGES];
__device__ __half g_W1h[(size_t)N_PAD * IN_DIM];    // W1^T fp16, [n][k], rows>=200 zero
__device__ float  g_H1[(size_t)N_NODES * HID];
__device__ float  g_H2[(size_t)N_NODES * OUT_DIM];
__device__ int    g_is64;

// ---------------- helpers ----------------------------------------------------
__device__ __forceinline__ int edge_at(const void* ei, size_t pos, int is64) {
    if (is64) return (int)((const long long*)ei)[pos];
    return ((const int*)ei)[pos];
}

__device__ __forceinline__ uint32_t smem_u32(const void* p) {
    uint32_t a;
    asm("{ .reg .u64 t; cvta.to.shared.u64 t, %1; cvt.u32.u64 %0, t; }"
        : "=r"(a) : "l"(p));
    return a;
}

__device__ __forceinline__ void cp16(uint32_t saddr, const void* g, int sz) {
    asm volatile("cp.async.cg.shared.global [%0], [%1], 16, %2;\n"
                 :: "r"(saddr), "l"(g), "r"(sz));
}

#define LDSM4(r0, r1, r2, r3, a)                                               \
    asm volatile("ldmatrix.sync.aligned.m8n8.x4.shared.b16 {%0,%1,%2,%3},[%4];"\
                 : "=r"(r0), "=r"(r1), "=r"(r2), "=r"(r3) : "r"(a))

#define LDSM2(r0, r1, a)                                                       \
    asm volatile("ldmatrix.sync.aligned.m8n8.x2.shared.b16 {%0,%1},[%2];"      \
                 : "=r"(r0), "=r"(r1) : "r"(a))

#define MMA16816(c, a, b)                                                      \
    asm volatile(                                                              \
        "mma.sync.aligned.m16n8k16.row.col.f32.f16.f16.f32 "                   \
        "{%0,%1,%2,%3},{%4,%5,%6,%7},{%8,%9},{%0,%1,%2,%3};\n"                 \
        : "+f"((c)[0]), "+f"((c)[1]), "+f"((c)[2]), "+f"((c)[3])               \
        : "r"((a)[0]), "r"((a)[1]), "r"((a)[2]), "r"((a)[3]),                  \
          "r"((b)[0]), "r"((b)[1]))

// ---------------- dtype detection --------------------------------------------
__global__ void detect_kernel(const unsigned* __restrict__ w, int n_check) {
    __shared__ int bad;
    if (threadIdx.x == 0) bad = 0;
    __syncthreads();
    int local = 0;
    for (int i = threadIdx.x; i < n_check; i += blockDim.x)
        if (w[2 * i + 1] != 0u) local = 1;
    if (local) bad = 1;
    __syncthreads();
    if (threadIdx.x == 0) g_is64 = bad ? 0 : 1;
}

// ---------------- degree + histogram init ------------------------------------
__global__ void init_kernel() {
    int i = blockIdx.x * blockDim.x + threadIdx.x;
    if (i < N_NODES) { g_dis[i] = 1.0f; g_cnt[i] = 0; }
}

// ---------------- W1 transpose + fp16 convert (padded to 224 rows) -----------
__global__ void w1t_kernel(const float* __restrict__ W1) {
    __shared__ float tile[32][33];
    int kb = blockIdx.y * 32, nb = blockIdx.x * 32;
    for (int j = threadIdx.y; j < 32; j += 8) {
        int k = kb + j, n = nb + threadIdx.x;
        tile[j][threadIdx.x] =
            (k < IN_DIM && n < HID) ? W1[(size_t)k * HID + n] : 0.f;
    }
    __syncthreads();
    for (int j = threadIdx.y; j < 32; j += 8) {
        int n = nb + j, k = kb + threadIdx.x;
        if (n < N_PAD && k < IN_DIM)
            g_W1h[(size_t)n * IN_DIM + k] = __float2half_rn(tile[threadIdx.x][j]);
    }
}

// ---------------- GEMM1: 128x224 CTA, BK=64, 8 warps (2x4), 1 CTA/SM ---------
#define G1T   256
#define G1_BM 128
#define G1_BK 64
#define G1_NT 121                   // ceil(7688/64)
#define SMA_BYTES (G1_BM * 128)     // 16384 per buffer
#define SMB_BYTES (N_PAD * 128)     // 28672 per buffer
#define G1_SMEM (2 * SMA_BYTES + 2 * SMB_BYTES)   // 90112

__global__ __launch_bounds__(G1T, 1)
void gemm1_kernel(const float* __restrict__ X) {
    extern __shared__ __align__(16) unsigned char smem[];
    unsigned char* smA = smem;                       // 2 x SMA_BYTES
    unsigned char* smB = smem + 2 * SMA_BYTES;       // 2 x SMB_BYTES
    const uint32_t smA0 = smem_u32(smA);
    const uint32_t smB0 = smem_u32(smB);

    const int tid  = threadIdx.x;
    const int lane = tid & 31;
    const int warp = tid >> 5;
    const int gid  = lane >> 2;
    const int tig  = lane & 3;
    const int wm   = warp >> 2;         // 0..1
    const int wn   = warp & 3;          // 0..3 (one per SMSP)
    const int m0   = blockIdx.x * G1_BM;

    // ---- A fill: 128 rows x 8 chunks(16B) = 1024 chunks = 4/thread ----------
    int aC[4];
    uint32_t aDst[4];
    bool aOkRow[4];
    const float* aSrc[4];
#pragma unroll
    for (int j = 0; j < 4; j++) {
        int idx = tid + j * G1T;
        int r = idx >> 3, c = idx & 7;
        aC[j] = c;
        aDst[j] = (uint32_t)(r * 128 + ((c ^ (r & 7)) << 4));
        aOkRow[j] = (m0 + r) < N_NODES;
        aSrc[j] = X + (size_t)(aOkRow[j] ? (m0 + r) : 0) * IN_DIM + c * 8;
    }

    float4 va[4][2];
    auto ldgA = [&](int k0) {
        const float4 z = make_float4(0.f, 0.f, 0.f, 0.f);
#pragma unroll
        for (int j = 0; j < 4; j++) {
            bool ok = aOkRow[j] && ((k0 + aC[j] * 8 + 8) <= IN_DIM);
            if (ok) {
                va[j][0] = *reinterpret_cast<const float4*>(aSrc[j] + k0);
                va[j][1] = *reinterpret_cast<const float4*>(aSrc[j] + k0 + 4);
            } else { va[j][0] = z; va[j][1] = z; }
        }
    };
    auto stsA = [&](int buf) {
        unsigned char* base = smA + buf * SMA_BYTES;
#pragma unroll
        for (int j = 0; j < 4; j++) {
            __half2 h0 = __floats2half2_rn(va[j][0].x, va[j][0].y);
            __half2 h1 = __floats2half2_rn(va[j][0].z, va[j][0].w);
            __half2 h2 = __floats2half2_rn(va[j][1].x, va[j][1].y);
            __half2 h3 = __floats2half2_rn(va[j][1].z, va[j][1].w);
            *reinterpret_cast<uint4*>(base + aDst[j]) =
                make_uint4(*(uint32_t*)&h0, *(uint32_t*)&h1,
                           *(uint32_t*)&h2, *(uint32_t*)&h3);
        }
    };
    // ---- B fill: 224 rows x 8 chunks = 1792 chunks = 7/thread ---------------
    auto cpB = [&](int k0, int buf) {
        const uint32_t bb = smB0 + (uint32_t)buf * SMB_BYTES;
#pragma unroll
        for (int j = 0; j < 7; j++) {
            int idx = tid + j * G1T;
            int n = idx >> 3, c = idx & 7;
            int ok = (k0 + c * 8 + 8) <= IN_DIM;
            const __half* src = g_W1h + (size_t)n * IN_DIM + (ok ? (k0 + c * 8) : 0);
            cp16(bb + (uint32_t)(n * 128 + ((c ^ (n & 7)) << 4)), src, ok ? 16 : 0);
        }
        asm volatile("cp.async.commit_group;\n");
    };

    // ---- fragment offsets ----------------------------------------------------
    uint32_t aRow[4];
#pragma unroll
    for (int mi = 0; mi < 4; mi++)
        aRow[mi] = (uint32_t)((wm * 64 + mi * 16 + (lane & 15)) * 128);
    // B pairs: LDSM4 p covers frags 2p,2p+1 (cols wn*56 + p*16 + 0..15)
    uint32_t bRow4[3], bRow2;
#pragma unroll
    for (int p = 0; p < 3; p++)
        bRow4[p] = (uint32_t)((wn * 56 + p * 16 + (lane & 7) + ((lane >> 4) << 3)) * 128);
    bRow2 = (uint32_t)((wn * 56 + 48 + (lane & 7)) * 128);
    const int xorR  = lane & 7;           // row&7 for all frag rows
    const int khalf = (lane >> 3) & 1;    // B k-half select
    const int khalfA = lane >> 4;         // A k-half select

    float c[4][7][4];
#pragma unroll
    for (int mi = 0; mi < 4; mi++)
#pragma unroll
        for (int ni = 0; ni < 7; ni++)
#pragma unroll
            for (int r = 0; r < 4; r++) c[mi][ni][r] = 0.0f;

    // ---- prologue ------------------------------------------------------------
    ldgA(0);
    cpB(0, 0);
    stsA(0);
    asm volatile("cp.async.wait_group 0;\n");
    __syncthreads();

    // ---- main loop: 121 iters, 4 k-steps each --------------------------------
    for (int t = 0; t < G1_NT; t++) {
        const int buf = t & 1;
        const bool more = (t + 1) < G1_NT;
        if (more) {
            ldgA((t + 1) * G1_BK);
            cpB((t + 1) * G1_BK, buf ^ 1);
        }
        const uint32_t ab = smA0 + (uint32_t)buf * SMA_BYTES;
        const uint32_t bb = smB0 + (uint32_t)buf * SMB_BYTES;

        uint32_t a[2][4][4], b[2][7][2];
        auto loadF = [&](int ks, int set) {
            uint32_t aoff = (uint32_t)(((ks * 2 + khalfA) ^ xorR) << 4);
            uint32_t boff = (uint32_t)(((ks * 2 + khalf) ^ xorR) << 4);
#pragma unroll
            for (int mi = 0; mi < 4; mi++)
                LDSM4(a[set][mi][0], a[set][mi][1], a[set][mi][2], a[set][mi][3],
                      ab + aRow[mi] + aoff);
#pragma unroll
            for (int p = 0; p < 3; p++)
                LDSM4(b[set][2 * p][0], b[set][2 * p][1],
                      b[set][2 * p + 1][0], b[set][2 * p + 1][1],
                      bb + bRow4[p] + boff);
            LDSM2(b[set][6][0], b[set][6][1], bb + bRow2 + boff);
        };
        loadF(0, 0);
#pragma unroll
        for (int ks = 0; ks < 4; ks++) {
            const int cur = ks & 1;
            if (ks < 3) loadF(ks + 1, cur ^ 1);
            if (ks == 3 && more) {
                stsA(buf ^ 1);                           // hide under final MMAs
                asm volatile("cp.async.wait_group 0;\n");
            }
#pragma unroll
            for (int mi = 0; mi < 4; mi++)
#pragma unroll
                for (int ni = 0; ni < 7; ni++)
                    MMA16816(c[mi][ni], a[cur][mi], b[cur][ni]);
        }
        __syncthreads();
    }

    // ---- epilogue (mask padded cols >= 200) ----------------------------------
#pragma unroll
    for (int mi = 0; mi < 4; mi++) {
        int r0 = m0 + wm * 64 + mi * 16 + gid;
        int r1 = r0 + 8;
#pragma unroll
        for (int ni = 0; ni < 7; ni++) {
            int col = wn * 56 + ni * 8 + 2 * tig;
            if (col >= HID) continue;
            if (r0 < N_NODES)
                *reinterpret_cast<float2*>(g_H1 + (size_t)r0 * HID + col) =
                    make_float2(c[mi][ni][0], c[mi][ni][1]);
            if (r1 < N_NODES)
                *reinterpret_cast<float2*>(g_H1 + (size_t)r1 * HID + col) =
                    make_float2(c[mi][ni][2], c[mi][ni][3]);
        }
    }
}

// ---------------- degree accumulate ------------------------------------------
__global__ void accum_kernel(const void* __restrict__ ei,
                             const float* __restrict__ ew) {
    int e = blockIdx.x * blockDim.x + threadIdx.x;
    if (e >= N_EDGES) return;
    int is64 = g_is64;
    int d = edge_at(ei, (size_t)N_EDGES + e, is64);
    atomicAdd(&g_dis[d], ew[e]);
    atomicAdd(&g_cnt[d], 1);
}

__global__ void rsqrt_kernel() {
    int i = blockIdx.x * blockDim.x + threadIdx.x;
    if (i < N_NODES) {
        float dg = g_dis[i];
        g_dis[i] = (dg > 0.0f) ? rsqrtf(dg) : 0.0f;
    }
}

// ---------------- exclusive scan (single block) ------------------------------
__global__ void scan_kernel() {
    __shared__ int part[1024];
    const int tid = threadIdx.x;
    const int CH = (N_NODES + 1023) / 1024;
    int base = tid * CH;
    int s = 0;
    for (int i = 0; i < CH; i++) {
        int idx = base + i;
        if (idx < N_NODES) s += g_cnt[idx];
    }
    part[tid] = s;
    __syncthreads();
    for (int off = 1; off < 1024; off <<= 1) {
        int v = (tid >= off) ? part[tid - off] : 0;
        __syncthreads();
        part[tid] += v;
        __syncthreads();
    }
    int ex = part[tid] - s;
    for (int i = 0; i < CH; i++) {
        int idx = base + i;
        if (idx < N_NODES) {
            g_off[idx] = ex;
            g_cur[idx] = ex;
            ex += g_cnt[idx];
        }
    }
    if (tid == 1023) g_off[N_NODES] = part[1023];
}

// ---------------- CSR fill ----------------------------------------------------
__global__ void fill_kernel(const void* __restrict__ ei,
                            const float* __restrict__ ew) {
    int e = blockIdx.x * blockDim.x + threadIdx.x;
    if (e >= N_EDGES) return;
    int is64 = g_is64;
    int s = edge_at(ei, e, is64);
    int d = edge_at(ei, (size_t)N_EDGES + e, is64);
    float w = g_dis[s] * ew[e] * g_dis[d];
    int pos = atomicAdd(&g_cur[d], 1);
    g_csr_src[pos] = s;
    g_csr_w[pos] = w;
}

// ---------------- prop1 + bias + relu + fused GEMM2 --------------------------
__global__ __launch_bounds__(224)
void prop1_kernel(const float* __restrict__ b1, const float* __restrict__ W2) {
    __shared__ float sh[HID];
    __shared__ float psum[64];
    const int n = blockIdx.x;
    const int col = threadIdx.x;

    if (col < HID) {
        float dv = g_dis[n];
        float acc = g_H1[(size_t)n * HID + col] * (dv * dv);
        int e = g_off[n], end = g_off[n + 1];
        for (; e + 4 <= end; e += 4) {
            int s0 = g_csr_src[e],     s1 = g_csr_src[e + 1];
            int s2 = g_csr_src[e + 2], s3 = g_csr_src[e + 3];
            float w0 = g_csr_w[e],     w1 = g_csr_w[e + 1];
            float w2 = g_csr_w[e + 2], w3 = g_csr_w[e + 3];
            float x0 = g_H1[(size_t)s0 * HID + col];
            float x1 = g_H1[(size_t)s1 * HID + col];
            float x2 = g_H1[(size_t)s2 * HID + col];
            float x3 = g_H1[(size_t)s3 * HID + col];
            acc += x0 * w0 + x1 * w1 + x2 * w2 + x3 * w3;
        }
        for (; e < end; e++)
            acc += g_H1[(size_t)g_csr_src[e] * HID + col] * g_csr_w[e];
        float v = acc + b1[col];
        sh[col] = v > 0.f ? v : 0.f;
    }
    __syncthreads();

    // fused GEMM2: H2[n] = h @ W2, 64 threads (8 outputs x 8 k-segments of 25)
    if (col < 64) {
        int o = col & 7, seg = col >> 3;
        float p = 0.f;
        int k0 = seg * 25;
#pragma unroll 5
        for (int k = k0; k < k0 + 25; k++)
            p += sh[k] * W2[k * OUT_DIM + o];
        psum[col] = p;
    }
    __syncthreads();
    if (col < OUT_DIM) {
        float s = 0.f;
#pragma unroll
        for (int j = 0; j < 8; j++) s += psum[j * 8 + col];
        g_H2[(size_t)n * OUT_DIM + col] = s;
    }
}

// ---------------- propagation 2 ----------------------------------------------
__global__ void prop2_kernel(const float* __restrict__ b2,
                             float* __restrict__ outp) {
    int n = blockIdx.x * 4 + (threadIdx.x >> 5);
    if (n >= N_NODES) return;
    int lane = threadIdx.x & 31;
    int sub = lane >> 3;
    int col = lane & 7;
    float acc = 0.f;
    int beg = g_off[n], end = g_off[n + 1];
    for (int e = beg + sub; e < end; e += 4)
        acc += g_H2[(size_t)g_csr_src[e] * OUT_DIM + col] * g_csr_w[e];
    acc += __shfl_xor_sync(0xffffffffu, acc, 8);
    acc += __shfl_xor_sync(0xffffffffu, acc, 16);
    if (sub == 0) {
        float dv = g_dis[n];
        outp[(size_t)n * OUT_DIM + col] =
            acc + g_H2[(size_t)n * OUT_DIM + col] * (dv * dv) + b2[col];
    }
}

// ---------------- launch -----------------------------------------------------
extern "C" void kernel_launch(void* const* d_in, const int* in_sizes, int n_in,
                              void* d_out, int out_size) {
    const float* x  = (const float*)d_in[0];
    const float* ew = (const float*)d_in[1];
    const float* W1 = (const float*)d_in[2];
    const float* b1 = (const float*)d_in[3];
    const float* W2 = (const float*)d_in[4];
    const float* b2 = (const float*)d_in[5];
    const void*  ei = d_in[6];
    float* outp = (float*)d_out;

    static cudaStream_t s1 = nullptr;
    static cudaEvent_t evFork = nullptr, evJoin = nullptr;
    if (!s1) {
        cudaStreamCreateWithFlags(&s1, cudaStreamNonBlocking);
        cudaEventCreateWithFlags(&evFork, cudaEventDisableTiming);
        cudaEventCreateWithFlags(&evJoin, cudaEventDisableTiming);
        cudaFuncSetAttribute(gemm1_kernel,
                             cudaFuncAttributeMaxDynamicSharedMemorySize, G1_SMEM);
    }

    cudaEventRecord(evFork, 0);
    cudaStreamWaitEvent(s1, evFork, 0);

    detect_kernel<<<1, 256, 0, s1>>>((const unsigned*)ei, 4096);
    init_kernel<<<(N_NODES + 255) / 256, 256, 0, s1>>>();
    w1t_kernel<<<dim3((N_PAD + 31) / 32, (IN_DIM + 31) / 32), dim3(32, 8)>>>(W1);
    gemm1_kernel<<<(N_NODES + G1_BM - 1) / G1_BM, G1T, G1_SMEM>>>(x);
    accum_kernel<<<(N_EDGES + 255) / 256, 256, 0, s1>>>(ei, ew);
    rsqrt_kernel<<<(N_NODES + 255) / 256, 256, 0, s1>>>();
    scan_kernel<<<1, 1024, 0, s1>>>();
    fill_kernel<<<(N_EDGES + 255) / 256, 256, 0, s1>>>(ei, ew);

    cudaEventRecord(evJoin, s1);
    cudaStreamWaitEvent(0, evJoin, 0);

    prop1_kernel<<<N_NODES, 224>>>(b1, W2);
    prop2_kernel<<<(N_NODES + 3) / 4, 128>>>(b2, outp);
}

// round 13
// speedup vs baseline: 1.9649x; 1.0878x over previous
#include <cuda_runtime.h>
#include <cuda_fp16.h>
#include <cstdint>

#define N_NODES 50000
#define IN_DIM  7688
#define HID     200
#define N_PAD   224
#define OUT_DIM 8
#define N_EDGES 1600000

// ---------------- scratch (device globals; no allocation allowed) -------------
__device__ float  g_dis[N_NODES];
__device__ int    g_cnt[N_NODES];
__device__ int    g_off[N_NODES + 1];
__device__ int    g_cur[N_NODES];
__device__ int    g_csr_src[N_EDGES];
__device__ float  g_csr_w[N_EDGES];
__device__ __half g_W1h[(size_t)N_PAD * IN_DIM];    // W1^T fp16, [n][k], rows>=200 zero
__device__ __half g_H1h[(size_t)N_NODES * HID];     // H1 in fp16
__device__ float  g_H2[(size_t)N_NODES * OUT_DIM];
__device__ int    g_is64;

// ---------------- helpers ----------------------------------------------------
__device__ __forceinline__ int edge_at(const void* ei, size_t pos, int is64) {
    if (is64) return (int)((const long long*)ei)[pos];
    return ((const int*)ei)[pos];
}

__device__ __forceinline__ uint32_t smem_u32(const void* p) {
    uint32_t a;
    asm("{ .reg .u64 t; cvta.to.shared.u64 t, %1; cvt.u32.u64 %0, t; }"
        : "=r"(a) : "l"(p));
    return a;
}

__device__ __forceinline__ void cp16(uint32_t saddr, const void* g, int sz) {
    asm volatile("cp.async.cg.shared.global [%0], [%1], 16, %2;\n"
                 :: "r"(saddr), "l"(g), "r"(sz));
}

#define LDSM4(r0, r1, r2, r3, a)                                               \
    asm volatile("ldmatrix.sync.aligned.m8n8.x4.shared.b16 {%0,%1,%2,%3},[%4];"\
                 : "=r"(r0), "=r"(r1), "=r"(r2), "=r"(r3) : "r"(a))

#define LDSM2(r0, r1, a)                                                       \
    asm volatile("ldmatrix.sync.aligned.m8n8.x2.shared.b16 {%0,%1},[%2];"      \
                 : "=r"(r0), "=r"(r1) : "r"(a))

#define MMA16816(c, a, b)                                                      \
    asm volatile(                                                              \
        "mma.sync.aligned.m16n8k16.row.col.f32.f16.f16.f32 "                   \
        "{%0,%1,%2,%3},{%4,%5,%6,%7},{%8,%9},{%0,%1,%2,%3};\n"                 \
        : "+f"((c)[0]), "+f"((c)[1]), "+f"((c)[2]), "+f"((c)[3])               \
        : "r"((a)[0]), "r"((a)[1]), "r"((a)[2]), "r"((a)[3]),                  \
          "r"((b)[0]), "r"((b)[1]))

// ---------------- dtype detection --------------------------------------------
__global__ void detect_kernel(const unsigned* __restrict__ w, int n_check) {
    __shared__ int bad;
    if (threadIdx.x == 0) bad = 0;
    __syncthreads();
    int local = 0;
    for (int i = threadIdx.x; i < n_check; i += blockDim.x)
        if (w[2 * i + 1] != 0u) local = 1;
    if (local) bad = 1;
    __syncthreads();
    if (threadIdx.x == 0) g_is64 = bad ? 0 : 1;
}

// ---------------- degree + histogram init ------------------------------------
__global__ void init_kernel() {
    int i = blockIdx.x * blockDim.x + threadIdx.x;
    if (i < N_NODES) { g_dis[i] = 1.0f; g_cnt[i] = 0; }
}

// ---------------- W1 transpose + fp16 convert (padded to 224 rows) -----------
__global__ void w1t_kernel(const float* __restrict__ W1) {
    __shared__ float tile[32][33];
    int kb = blockIdx.y * 32, nb = blockIdx.x * 32;
    for (int j = threadIdx.y; j < 32; j += 8) {
        int k = kb + j, n = nb + threadIdx.x;
        tile[j][threadIdx.x] =
            (k < IN_DIM && n < HID) ? W1[(size_t)k * HID + n] : 0.f;
    }
    __syncthreads();
    for (int j = threadIdx.y; j < 32; j += 8) {
        int n = nb + j, k = kb + threadIdx.x;
        if (n < N_PAD && k < IN_DIM)
            g_W1h[(size_t)n * IN_DIM + k] = __float2half_rn(tile[threadIdx.x][j]);
    }
}

// ---------------- GEMM1: 128x224 CTA, BK=64, 8 warps (2x4), 1 CTA/SM ---------
#define G1T   256
#define G1_BM 128
#define G1_BK 64
#define G1_NT 121                   // ceil(7688/64)
#define SMA_BYTES (G1_BM * 128)     // 16384 per buffer
#define SMB_BYTES (N_PAD * 128)     // 28672 per buffer
#define G1_SMEM (2 * SMA_BYTES + 2 * SMB_BYTES)   // 90112

__global__ __launch_bounds__(G1T, 1)
void gemm1_kernel(const float* __restrict__ X) {
    extern __shared__ __align__(16) unsigned char smem[];
    unsigned char* smA = smem;                       // 2 x SMA_BYTES
    unsigned char* smB = smem + 2 * SMA_BYTES;       // 2 x SMB_BYTES
    const uint32_t smA0 = smem_u32(smA);
    const uint32_t smB0 = smem_u32(smB);

    const int tid  = threadIdx.x;
    const int lane = tid & 31;
    const int warp = tid >> 5;
    const int gid  = lane >> 2;
    const int tig  = lane & 3;
    const int wm   = warp >> 2;         // 0..1
    const int wn   = warp & 3;          // 0..3 (one per SMSP)
    const int m0   = blockIdx.x * G1_BM;

    // ---- A fill: 128 rows x 8 chunks(16B) = 1024 chunks = 4/thread ----------
    int aC[4];
    uint32_t aDst[4];
    bool aOkRow[4];
    const float* aSrc[4];
#pragma unroll
    for (int j = 0; j < 4; j++) {
        int idx = tid + j * G1T;
        int r = idx >> 3, c = idx & 7;
        aC[j] = c;
        aDst[j] = (uint32_t)(r * 128 + ((c ^ (r & 7)) << 4));
        aOkRow[j] = (m0 + r) < N_NODES;
        aSrc[j] = X + (size_t)(aOkRow[j] ? (m0 + r) : 0) * IN_DIM + c * 8;
    }

    float4 va[4][2];
    auto ldgA = [&](int k0) {
        const float4 z = make_float4(0.f, 0.f, 0.f, 0.f);
#pragma unroll
        for (int j = 0; j < 4; j++) {
            bool ok = aOkRow[j] && ((k0 + aC[j] * 8 + 8) <= IN_DIM);
            if (ok) {
                va[j][0] = *reinterpret_cast<const float4*>(aSrc[j] + k0);
                va[j][1] = *reinterpret_cast<const float4*>(aSrc[j] + k0 + 4);
            } else { va[j][0] = z; va[j][1] = z; }
        }
    };
    auto stsA = [&](int buf) {
        unsigned char* base = smA + buf * SMA_BYTES;
#pragma unroll
        for (int j = 0; j < 4; j++) {
            __half2 h0 = __floats2half2_rn(va[j][0].x, va[j][0].y);
            __half2 h1 = __floats2half2_rn(va[j][0].z, va[j][0].w);
            __half2 h2 = __floats2half2_rn(va[j][1].x, va[j][1].y);
            __half2 h3 = __floats2half2_rn(va[j][1].z, va[j][1].w);
            *reinterpret_cast<uint4*>(base + aDst[j]) =
                make_uint4(*(uint32_t*)&h0, *(uint32_t*)&h1,
                           *(uint32_t*)&h2, *(uint32_t*)&h3);
        }
    };
    // ---- B fill: 224 rows x 8 chunks = 1792 chunks = 7/thread ---------------
    auto cpB = [&](int k0, int buf) {
        const uint32_t bb = smB0 + (uint32_t)buf * SMB_BYTES;
#pragma unroll
        for (int j = 0; j < 7; j++) {
            int idx = tid + j * G1T;
            int n = idx >> 3, c = idx & 7;
            int ok = (k0 + c * 8 + 8) <= IN_DIM;
            const __half* src = g_W1h + (size_t)n * IN_DIM + (ok ? (k0 + c * 8) : 0);
            cp16(bb + (uint32_t)(n * 128 + ((c ^ (n & 7)) << 4)), src, ok ? 16 : 0);
        }
        asm volatile("cp.async.commit_group;\n");
    };

    // ---- fragment offsets ----------------------------------------------------
    uint32_t aRow[4];
#pragma unroll
    for (int mi = 0; mi < 4; mi++)
        aRow[mi] = (uint32_t)((wm * 64 + mi * 16 + (lane & 15)) * 128);
    uint32_t bRow4[3], bRow2;
#pragma unroll
    for (int p = 0; p < 3; p++)
        bRow4[p] = (uint32_t)((wn * 56 + p * 16 + (lane & 7) + ((lane >> 4) << 3)) * 128);
    bRow2 = (uint32_t)((wn * 56 + 48 + (lane & 7)) * 128);
    const int xorR  = lane & 7;
    const int khalf = (lane >> 3) & 1;
    const int khalfA = lane >> 4;

    float c[4][7][4];
#pragma unroll
    for (int mi = 0; mi < 4; mi++)
#pragma unroll
        for (int ni = 0; ni < 7; ni++)
#pragma unroll
            for (int r = 0; r < 4; r++) c[mi][ni][r] = 0.0f;

    // ---- prologue ------------------------------------------------------------
    ldgA(0);
    cpB(0, 0);
    stsA(0);
    asm volatile("cp.async.wait_group 0;\n");
    __syncthreads();

    // ---- main loop ------------------------------------------------------------
    for (int t = 0; t < G1_NT; t++) {
        const int buf = t & 1;
        const bool more = (t + 1) < G1_NT;
        if (more) {
            ldgA((t + 1) * G1_BK);
            cpB((t + 1) * G1_BK, buf ^ 1);
        }
        const uint32_t ab = smA0 + (uint32_t)buf * SMA_BYTES;
        const uint32_t bb = smB0 + (uint32_t)buf * SMB_BYTES;

        uint32_t a[2][4][4], b[2][7][2];
        auto loadF = [&](int ks, int set) {
            uint32_t aoff = (uint32_t)(((ks * 2 + khalfA) ^ xorR) << 4);
            uint32_t boff = (uint32_t)(((ks * 2 + khalf) ^ xorR) << 4);
#pragma unroll
            for (int mi = 0; mi < 4; mi++)
                LDSM4(a[set][mi][0], a[set][mi][1], a[set][mi][2], a[set][mi][3],
                      ab + aRow[mi] + aoff);
#pragma unroll
            for (int p = 0; p < 3; p++)
                LDSM4(b[set][2 * p][0], b[set][2 * p][1],
                      b[set][2 * p + 1][0], b[set][2 * p + 1][1],
                      bb + bRow4[p] + boff);
            LDSM2(b[set][6][0], b[set][6][1], bb + bRow2 + boff);
        };
        loadF(0, 0);
#pragma unroll
        for (int ks = 0; ks < 4; ks++) {
            const int cur = ks & 1;
            if (ks < 3) loadF(ks + 1, cur ^ 1);
            if (ks == 3 && more) {
                stsA(buf ^ 1);
                asm volatile("cp.async.wait_group 0;\n");
            }
#pragma unroll
            for (int mi = 0; mi < 4; mi++)
#pragma unroll
                for (int ni = 0; ni < 7; ni++)
                    MMA16816(c[mi][ni], a[cur][mi], b[cur][ni]);
        }
        __syncthreads();
    }

    // ---- epilogue: store H1 as fp16 (mask cols >= 200) -----------------------
#pragma unroll
    for (int mi = 0; mi < 4; mi++) {
        int r0 = m0 + wm * 64 + mi * 16 + gid;
        int r1 = r0 + 8;
#pragma unroll
        for (int ni = 0; ni < 7; ni++) {
            int col = wn * 56 + ni * 8 + 2 * tig;
            if (col >= HID) continue;
            if (r0 < N_NODES) {
                __half2 h = __floats2half2_rn(c[mi][ni][0], c[mi][ni][1]);
                *reinterpret_cast<__half2*>(g_H1h + (size_t)r0 * HID + col) = h;
            }
            if (r1 < N_NODES) {
                __half2 h = __floats2half2_rn(c[mi][ni][2], c[mi][ni][3]);
                *reinterpret_cast<__half2*>(g_H1h + (size_t)r1 * HID + col) = h;
            }
        }
    }
}

// ---------------- degree accumulate ------------------------------------------
__global__ void accum_kernel(const void* __restrict__ ei,
                             const float* __restrict__ ew) {
    int e = blockIdx.x * blockDim.x + threadIdx.x;
    if (e >= N_EDGES) return;
    int is64 = g_is64;
    int d = edge_at(ei, (size_t)N_EDGES + e, is64);
    atomicAdd(&g_dis[d], ew[e]);
    atomicAdd(&g_cnt[d], 1);
}

__global__ void rsqrt_kernel() {
    int i = blockIdx.x * blockDim.x + threadIdx.x;
    if (i < N_NODES) {
        float dg = g_dis[i];
        g_dis[i] = (dg > 0.0f) ? rsqrtf(dg) : 0.0f;
    }
}

// ---------------- exclusive scan (single block) ------------------------------
__global__ void scan_kernel() {
    __shared__ int part[1024];
    const int tid = threadIdx.x;
    const int CH = (N_NODES + 1023) / 1024;
    int base = tid * CH;
    int s = 0;
    for (int i = 0; i < CH; i++) {
        int idx = base + i;
        if (idx < N_NODES) s += g_cnt[idx];
    }
    part[tid] = s;
    __syncthreads();
    for (int off = 1; off < 1024; off <<= 1) {
        int v = (tid >= off) ? part[tid - off] : 0;
        __syncthreads();
        part[tid] += v;
        __syncthreads();
    }
    int ex = part[tid] - s;
    for (int i = 0; i < CH; i++) {
        int idx = base + i;
        if (idx < N_NODES) {
            g_off[idx] = ex;
            g_cur[idx] = ex;
            ex += g_cnt[idx];
        }
    }
    if (tid == 1023) g_off[N_NODES] = part[1023];
}

// ---------------- CSR fill ----------------------------------------------------
__global__ void fill_kernel(const void* __restrict__ ei,
                            const float* __restrict__ ew) {
    int e = blockIdx.x * blockDim.x + threadIdx.x;
    if (e >= N_EDGES) return;
    int is64 = g_is64;
    int s = edge_at(ei, e, is64);
    int d = edge_at(ei, (size_t)N_EDGES + e, is64);
    float w = g_dis[s] * ew[e] * g_dis[d];
    int pos = atomicAdd(&g_cur[d], 1);
    g_csr_src[pos] = s;
    g_csr_w[pos] = w;
}

// ---------------- prop1 (fp16 gather, 2 cols/thread) + relu + fused GEMM2 ----
__global__ __launch_bounds__(128)
void prop1_kernel(const float* __restrict__ b1, const float* __restrict__ W2) {
    __shared__ float sh[HID];
    __shared__ float psum[64];
    const int n = blockIdx.x;
    const int tid = threadIdx.x;

    if (tid < HID / 2) {
        const int col = tid * 2;
        float dv = g_dis[n];
        float s2 = dv * dv;
        __half2 hv = *reinterpret_cast<const __half2*>(g_H1h + (size_t)n * HID + col);
        float2 hf = __half22float2(hv);
        float acc0 = hf.x * s2, acc1 = hf.y * s2;
        int e = g_off[n], end = g_off[n + 1];
        for (; e + 2 <= end; e += 2) {
            int s0 = g_csr_src[e], s1 = g_csr_src[e + 1];
            float w0 = g_csr_w[e], w1 = g_csr_w[e + 1];
            float2 x0 = __half22float2(
                *reinterpret_cast<const __half2*>(g_H1h + (size_t)s0 * HID + col));
            float2 x1 = __half22float2(
                *reinterpret_cast<const __half2*>(g_H1h + (size_t)s1 * HID + col));
            acc0 += x0.x * w0 + x1.x * w1;
            acc1 += x0.y * w0 + x1.y * w1;
        }
        if (e < end) {
            int s0 = g_csr_src[e];
            float w0 = g_csr_w[e];
            float2 x0 = __half22float2(
                *reinterpret_cast<const __half2*>(g_H1h + (size_t)s0 * HID + col));
            acc0 += x0.x * w0;
            acc1 += x0.y * w0;
        }
        float v0 = acc0 + b1[col];
        float v1 = acc1 + b1[col + 1];
        sh[col]     = v0 > 0.f ? v0 : 0.f;
        sh[col + 1] = v1 > 0.f ? v1 : 0.f;
    }
    __syncthreads();

    // fused GEMM2: H2[n] = h @ W2, 64 threads (8 outputs x 8 k-segments of 25)
    if (tid < 64) {
        int o = tid & 7, seg = tid >> 3;
        float p = 0.f;
        int k0 = seg * 25;
#pragma unroll 5
        for (int k = k0; k < k0 + 25; k++)
            p += sh[k] * W2[k * OUT_DIM + o];
        psum[tid] = p;
    }
    __syncthreads();
    if (tid < OUT_DIM) {
        float s = 0.f;
#pragma unroll
        for (int j = 0; j < 8; j++) s += psum[j * 8 + tid];
        g_H2[(size_t)n * OUT_DIM + tid] = s;
    }
}

// ---------------- propagation 2 ----------------------------------------------
__global__ void prop2_kernel(const float* __restrict__ b2,
                             float* __restrict__ outp) {
    int n = blockIdx.x * 4 + (threadIdx.x >> 5);
    if (n >= N_NODES) return;
    int lane = threadIdx.x & 31;
    int sub = lane >> 3;
    int col = lane & 7;
    float acc = 0.f;
    int beg = g_off[n], end = g_off[n + 1];
    for (int e = beg + sub; e < end; e += 4)
        acc += g_H2[(size_t)g_csr_src[e] * OUT_DIM + col] * g_csr_w[e];
    acc += __shfl_xor_sync(0xffffffffu, acc, 8);
    acc += __shfl_xor_sync(0xffffffffu, acc, 16);
    if (sub == 0) {
        float dv = g_dis[n];
        outp[(size_t)n * OUT_DIM + col] =
            acc + g_H2[(size_t)n * OUT_DIM + col] * (dv * dv) + b2[col];
    }
}

// ---------------- launch -----------------------------------------------------
extern "C" void kernel_launch(void* const* d_in, const int* in_sizes, int n_in,
                              void* d_out, int out_size) {
    const float* x  = (const float*)d_in[0];
    const float* ew = (const float*)d_in[1];
    const float* W1 = (const float*)d_in[2];
    const float* b1 = (const float*)d_in[3];
    const float* W2 = (const float*)d_in[4];
    const float* b2 = (const float*)d_in[5];
    const void*  ei = d_in[6];
    float* outp = (float*)d_out;

    static cudaStream_t s1 = nullptr;
    static cudaEvent_t evFork = nullptr, evJoin = nullptr;
    if (!s1) {
        cudaStreamCreateWithFlags(&s1, cudaStreamNonBlocking);
        cudaEventCreateWithFlags(&evFork, cudaEventDisableTiming);
        cudaEventCreateWithFlags(&evJoin, cudaEventDisableTiming);
        cudaFuncSetAttribute(gemm1_kernel,
                             cudaFuncAttributeMaxDynamicSharedMemorySize, G1_SMEM);
    }

    cudaEventRecord(evFork, 0);
    cudaStreamWaitEvent(s1, evFork, 0);

    detect_kernel<<<1, 256, 0, s1>>>((const unsigned*)ei, 4096);
    init_kernel<<<(N_NODES + 255) / 256, 256, 0, s1>>>();
    w1t_kernel<<<dim3((N_PAD + 31) / 32, (IN_DIM + 31) / 32), dim3(32, 8)>>>(W1);
    gemm1_kernel<<<(N_NODES + G1_BM - 1) / G1_BM, G1T, G1_SMEM>>>(x);
    accum_kernel<<<(N_EDGES + 255) / 256, 256, 0, s1>>>(ei, ew);
    rsqrt_kernel<<<(N_NODES + 255) / 256, 256, 0, s1>>>();
    scan_kernel<<<1, 1024, 0, s1>>>();
    fill_kernel<<<(N_EDGES + 255) / 256, 256, 0, s1>>>(ei, ew);

    cudaEventRecord(evJoin, s1);
    cudaStreamWaitEvent(0, evJoin, 0);

    prop1_kernel<<<N_NODES, 128>>>(b1, W2);
    prop2_kernel<<<(N_NODES + 3) / 4, 128>>>(b2, outp);
}

// round 15
// speedup vs baseline: 2.0619x; 1.0493x over previous
#include <cuda_runtime.h>
#include <cuda_fp16.h>
#include <cstdint>

#define N_NODES 50000
#define IN_DIM  7688
#define HID     200
#define N_PAD   224
#define OUT_DIM 8
#define N_EDGES 1600000

// ---------------- scratch (device globals; no allocation allowed) -------------
__device__ float  g_dis[N_NODES];
__device__ int    g_cnt[N_NODES];
__device__ int    g_off[N_NODES + 1];
__device__ int    g_cur[N_NODES];
__device__ int    g_csr_src[N_EDGES];
__device__ float  g_csr_w[N_EDGES];
__device__ __half g_W1h[(size_t)N_PAD * IN_DIM];    // W1^T fp16, [n][k], rows>=200 zero
__device__ __half g_H1h[(size_t)N_NODES * HID];     // H1 in fp16
__device__ __half g_H2h[(size_t)N_NODES * OUT_DIM]; // H2 in fp16
__device__ int    g_is64;

// ---------------- helpers ----------------------------------------------------
__device__ __forceinline__ int edge_at(const void* ei, size_t pos, int is64) {
    if (is64) return (int)((const long long*)ei)[pos];
    return ((const int*)ei)[pos];
}

__device__ __forceinline__ uint32_t smem_u32(const void* p) {
    uint32_t a;
    asm("{ .reg .u64 t; cvta.to.shared.u64 t, %1; cvt.u32.u64 %0, t; }"
        : "=r"(a) : "l"(p));
    return a;
}

__device__ __forceinline__ void cp16(uint32_t saddr, const void* g, int sz) {
    asm volatile("cp.async.cg.shared.global [%0], [%1], 16, %2;\n"
                 :: "r"(saddr), "l"(g), "r"(sz));
}

#define LDSM4(r0, r1, r2, r3, a)                                               \
    asm volatile("ldmatrix.sync.aligned.m8n8.x4.shared.b16 {%0,%1,%2,%3},[%4];"\
                 : "=r"(r0), "=r"(r1), "=r"(r2), "=r"(r3) : "r"(a))

#define LDSM2(r0, r1, a)                                                       \
    asm volatile("ldmatrix.sync.aligned.m8n8.x2.shared.b16 {%0,%1},[%2];"      \
                 : "=r"(r0), "=r"(r1) : "r"(a))

#define MMA16816(c, a, b)                                                      \
    asm volatile(                                                              \
        "mma.sync.aligned.m16n8k16.row.col.f32.f16.f16.f32 "                   \
        "{%0,%1,%2,%3},{%4,%5,%6,%7},{%8,%9},{%0,%1,%2,%3};\n"                 \
        : "+f"((c)[0]), "+f"((c)[1]), "+f"((c)[2]), "+f"((c)[3])               \
        : "r"((a)[0]), "r"((a)[1]), "r"((a)[2]), "r"((a)[3]),                  \
          "r"((b)[0]), "r"((b)[1]))

// ---------------- dtype detection --------------------------------------------
__global__ void detect_kernel(const unsigned* __restrict__ w, int n_check) {
    __shared__ int bad;
    if (threadIdx.x == 0) bad = 0;
    __syncthreads();
    int local = 0;
    for (int i = threadIdx.x; i < n_check; i += blockDim.x)
        if (w[2 * i + 1] != 0u) local = 1;
    if (local) bad = 1;
    __syncthreads();
    if (threadIdx.x == 0) g_is64 = bad ? 0 : 1;
}

// ---------------- degree + histogram init ------------------------------------
__global__ void init_kernel() {
    int i = blockIdx.x * blockDim.x + threadIdx.x;
    if (i < N_NODES) { g_dis[i] = 1.0f; g_cnt[i] = 0; }
}

// ---------------- W1 transpose + fp16 convert (padded to 224 rows) -----------
__global__ void w1t_kernel(const float* __restrict__ W1) {
    __shared__ float tile[32][33];
    int kb = blockIdx.y * 32, nb = blockIdx.x * 32;
    for (int j = threadIdx.y; j < 32; j += 8) {
        int k = kb + j, n = nb + threadIdx.x;
        tile[j][threadIdx.x] =
            (k < IN_DIM && n < HID) ? W1[(size_t)k * HID + n] : 0.f;
    }
    __syncthreads();
    for (int j = threadIdx.y; j < 32; j += 8) {
        int n = nb + j, k = kb + threadIdx.x;
        if (n < N_PAD && k < IN_DIM)
            g_W1h[(size_t)n * IN_DIM + k] = __float2half_rn(tile[threadIdx.x][j]);
    }
}

// ---------------- GEMM1: 128x224 CTA, BK=64, 8 warps (2x4), 1 CTA/SM ---------
#define G1T   256
#define G1_BM 128
#define G1_BK 64
#define G1_NT 121
#define SMA_BYTES (G1_BM * 128)
#define SMB_BYTES (N_PAD * 128)
#define G1_SMEM (2 * SMA_BYTES + 2 * SMB_BYTES)

__global__ __launch_bounds__(G1T, 1)
void gemm1_kernel(const float* __restrict__ X) {
    extern __shared__ __align__(16) unsigned char smem[];
    unsigned char* smA = smem;
    unsigned char* smB = smem + 2 * SMA_BYTES;
    const uint32_t smA0 = smem_u32(smA);
    const uint32_t smB0 = smem_u32(smB);

    const int tid  = threadIdx.x;
    const int lane = tid & 31;
    const int warp = tid >> 5;
    const int gid  = lane >> 2;
    const int tig  = lane & 3;
    const int wm   = warp >> 2;
    const int wn   = warp & 3;
    const int m0   = blockIdx.x * G1_BM;

    int aC[4];
    uint32_t aDst[4];
    bool aOkRow[4];
    const float* aSrc[4];
#pragma unroll
    for (int j = 0; j < 4; j++) {
        int idx = tid + j * G1T;
        int r = idx >> 3, c = idx & 7;
        aC[j] = c;
        aDst[j] = (uint32_t)(r * 128 + ((c ^ (r & 7)) << 4));
        aOkRow[j] = (m0 + r) < N_NODES;
        aSrc[j] = X + (size_t)(aOkRow[j] ? (m0 + r) : 0) * IN_DIM + c * 8;
    }

    float4 va[4][2];
    auto ldgA = [&](int k0) {
        const float4 z = make_float4(0.f, 0.f, 0.f, 0.f);
#pragma unroll
        for (int j = 0; j < 4; j++) {
            bool ok = aOkRow[j] && ((k0 + aC[j] * 8 + 8) <= IN_DIM);
            if (ok) {
                va[j][0] = *reinterpret_cast<const float4*>(aSrc[j] + k0);
                va[j][1] = *reinterpret_cast<const float4*>(aSrc[j] + k0 + 4);
            } else { va[j][0] = z; va[j][1] = z; }
        }
    };
    auto stsA = [&](int buf) {
        unsigned char* base = smA + buf * SMA_BYTES;
#pragma unroll
        for (int j = 0; j < 4; j++) {
            __half2 h0 = __floats2half2_rn(va[j][0].x, va[j][0].y);
            __half2 h1 = __floats2half2_rn(va[j][0].z, va[j][0].w);
            __half2 h2 = __floats2half2_rn(va[j][1].x, va[j][1].y);
            __half2 h3 = __floats2half2_rn(va[j][1].z, va[j][1].w);
            *reinterpret_cast<uint4*>(base + aDst[j]) =
                make_uint4(*(uint32_t*)&h0, *(uint32_t*)&h1,
                           *(uint32_t*)&h2, *(uint32_t*)&h3);
        }
    };
    auto cpB = [&](int k0, int buf) {
        const uint32_t bb = smB0 + (uint32_t)buf * SMB_BYTES;
#pragma unroll
        for (int j = 0; j < 7; j++) {
            int idx = tid + j * G1T;
            int n = idx >> 3, c = idx & 7;
            int ok = (k0 + c * 8 + 8) <= IN_DIM;
            const __half* src = g_W1h + (size_t)n * IN_DIM + (ok ? (k0 + c * 8) : 0);
            cp16(bb + (uint32_t)(n * 128 + ((c ^ (n & 7)) << 4)), src, ok ? 16 : 0);
        }
        asm volatile("cp.async.commit_group;\n");
    };

    uint32_t aRow[4];
#pragma unroll
    for (int mi = 0; mi < 4; mi++)
        aRow[mi] = (uint32_t)((wm * 64 + mi * 16 + (lane & 15)) * 128);
    uint32_t bRow4[3], bRow2;
#pragma unroll
    for (int p = 0; p < 3; p++)
        bRow4[p] = (uint32_t)((wn * 56 + p * 16 + (lane & 7) + ((lane >> 4) << 3)) * 128);
    bRow2 = (uint32_t)((wn * 56 + 48 + (lane & 7)) * 128);
    const int xorR  = lane & 7;
    const int khalf = (lane >> 3) & 1;
    const int khalfA = lane >> 4;

    float c[4][7][4];
#pragma unroll
    for (int mi = 0; mi < 4; mi++)
#pragma unroll
        for (int ni = 0; ni < 7; ni++)
#pragma unroll
            for (int r = 0; r < 4; r++) c[mi][ni][r] = 0.0f;

    ldgA(0);
    cpB(0, 0);
    stsA(0);
    asm volatile("cp.async.wait_group 0;\n");
    __syncthreads();

    for (int t = 0; t < G1_NT; t++) {
        const int buf = t & 1;
        const bool more = (t + 1) < G1_NT;
        if (more) {
            ldgA((t + 1) * G1_BK);
            cpB((t + 1) * G1_BK, buf ^ 1);
        }
        const uint32_t ab = smA0 + (uint32_t)buf * SMA_BYTES;
        const uint32_t bb = smB0 + (uint32_t)buf * SMB_BYTES;

        uint32_t a[2][4][4], b[2][7][2];
        auto loadF = [&](int ks, int set) {
            uint32_t aoff = (uint32_t)(((ks * 2 + khalfA) ^ xorR) << 4);
            uint32_t boff = (uint32_t)(((ks * 2 + khalf) ^ xorR) << 4);
#pragma unroll
            for (int mi = 0; mi < 4; mi++)
                LDSM4(a[set][mi][0], a[set][mi][1], a[set][mi][2], a[set][mi][3],
                      ab + aRow[mi] + aoff);
#pragma unroll
            for (int p = 0; p < 3; p++)
                LDSM4(b[set][2 * p][0], b[set][2 * p][1],
                      b[set][2 * p + 1][0], b[set][2 * p + 1][1],
                      bb + bRow4[p] + boff);
            LDSM2(b[set][6][0], b[set][6][1], bb + bRow2 + boff);
        };
        loadF(0, 0);
#pragma unroll
        for (int ks = 0; ks < 4; ks++) {
            const int cur = ks & 1;
            if (ks < 3) loadF(ks + 1, cur ^ 1);
            if (ks == 3 && more) {
                stsA(buf ^ 1);
                asm volatile("cp.async.wait_group 0;\n");
            }
#pragma unroll
            for (int mi = 0; mi < 4; mi++)
#pragma unroll
                for (int ni = 0; ni < 7; ni++)
                    MMA16816(c[mi][ni], a[cur][mi], b[cur][ni]);
        }
        __syncthreads();
    }

    // epilogue: store H1 as fp16 (mask cols >= 200)
#pragma unroll
    for (int mi = 0; mi < 4; mi++) {
        int r0 = m0 + wm * 64 + mi * 16 + gid;
        int r1 = r0 + 8;
#pragma unroll
        for (int ni = 0; ni < 7; ni++) {
            int col = wn * 56 + ni * 8 + 2 * tig;
            if (col >= HID) continue;
            if (r0 < N_NODES) {
                __half2 h = __floats2half2_rn(c[mi][ni][0], c[mi][ni][1]);
                *reinterpret_cast<__half2*>(g_H1h + (size_t)r0 * HID + col) = h;
            }
            if (r1 < N_NODES) {
                __half2 h = __floats2half2_rn(c[mi][ni][2], c[mi][ni][3]);
                *reinterpret_cast<__half2*>(g_H1h + (size_t)r1 * HID + col) = h;
            }
        }
    }
}

// ---------------- degree accumulate ------------------------------------------
__global__ void accum_kernel(const void* __restrict__ ei,
                             const float* __restrict__ ew) {
    int e = blockIdx.x * blockDim.x + threadIdx.x;
    if (e >= N_EDGES) return;
    int is64 = g_is64;
    int d = edge_at(ei, (size_t)N_EDGES + e, is64);
    atomicAdd(&g_dis[d], ew[e]);
    atomicAdd(&g_cnt[d], 1);
}

__global__ void rsqrt_kernel() {
    int i = blockIdx.x * blockDim.x + threadIdx.x;
    if (i < N_NODES) {
        float dg = g_dis[i];
        g_dis[i] = (dg > 0.0f) ? rsqrtf(dg) : 0.0f;
    }
}

// ---------------- exclusive scan (single block) ------------------------------
__global__ void scan_kernel() {
    __shared__ int part[1024];
    const int tid = threadIdx.x;
    const int CH = (N_NODES + 1023) / 1024;
    int base = tid * CH;
    int s = 0;
    for (int i = 0; i < CH; i++) {
        int idx = base + i;
        if (idx < N_NODES) s += g_cnt[idx];
    }
    part[tid] = s;
    __syncthreads();
    for (int off = 1; off < 1024; off <<= 1) {
        int v = (tid >= off) ? part[tid - off] : 0;
        __syncthreads();
        part[tid] += v;
        __syncthreads();
    }
    int ex = part[tid] - s;
    for (int i = 0; i < CH; i++) {
        int idx = base + i;
        if (idx < N_NODES) {
            g_off[idx] = ex;
            g_cur[idx] = ex;
            ex += g_cnt[idx];
        }
    }
    if (tid == 1023) g_off[N_NODES] = part[1023];
}

// ---------------- CSR fill ----------------------------------------------------
__global__ void fill_kernel(const void* __restrict__ ei,
                            const float* __restrict__ ew) {
    int e = blockIdx.x * blockDim.x + threadIdx.x;
    if (e >= N_EDGES) return;
    int is64 = g_is64;
    int s = edge_at(ei, e, is64);
    int d = edge_at(ei, (size_t)N_EDGES + e, is64);
    float w = g_dis[s] * ew[e] * g_dis[d];
    int pos = atomicAdd(&g_cur[d], 1);
    g_csr_src[pos] = s;
    g_csr_w[pos] = w;
}

// ---------------- prop1 (fp16 gather, 4 cols/thread) + relu + fused GEMM2 ----
__global__ __launch_bounds__(64)
void prop1_kernel(const float* __restrict__ b1, const float* __restrict__ W2) {
    __shared__ float sh[HID];
    __shared__ float psum[64];
    const int n = blockIdx.x;
    const int tid = threadIdx.x;

    if (tid < HID / 4) {
        const int col = tid * 4;   // 4 halves = 8 bytes
        float dv = g_dis[n];
        float s2 = dv * dv;
        uint2 hv = *reinterpret_cast<const uint2*>(g_H1h + (size_t)n * HID + col);
        float2 ha = __half22float2(*(const __half2*)&hv.x);
        float2 hb = __half22float2(*(const __half2*)&hv.y);
        float a0 = ha.x * s2, a1 = ha.y * s2, a2 = hb.x * s2, a3 = hb.y * s2;
        int e = g_off[n], end = g_off[n + 1];
        for (; e + 2 <= end; e += 2) {
            int s0 = g_csr_src[e], s1 = g_csr_src[e + 1];
            float w0 = g_csr_w[e], w1 = g_csr_w[e + 1];
            uint2 x0 = *reinterpret_cast<const uint2*>(g_H1h + (size_t)s0 * HID + col);
            uint2 x1 = *reinterpret_cast<const uint2*>(g_H1h + (size_t)s1 * HID + col);
            float2 x0a = __half22float2(*(const __half2*)&x0.x);
            float2 x0b = __half22float2(*(const __half2*)&x0.y);
            float2 x1a = __half22float2(*(const __half2*)&x1.x);
            float2 x1b = __half22float2(*(const __half2*)&x1.y);
            a0 += x0a.x * w0 + x1a.x * w1;
            a1 += x0a.y * w0 + x1a.y * w1;
            a2 += x0b.x * w0 + x1b.x * w1;
            a3 += x0b.y * w0 + x1b.y * w1;
        }
        if (e < end) {
            int s0 = g_csr_src[e];
            float w0 = g_csr_w[e];
            uint2 x0 = *reinterpret_cast<const uint2*>(g_H1h + (size_t)s0 * HID + col);
            float2 x0a = __half22float2(*(const __half2*)&x0.x);
            float2 x0b = __half22float2(*(const __half2*)&x0.y);
            a0 += x0a.x * w0; a1 += x0a.y * w0;
            a2 += x0b.x * w0; a3 += x0b.y * w0;
        }
        float4 bv = *reinterpret_cast<const float4*>(b1 + col);
        float v0 = a0 + bv.x, v1 = a1 + bv.y, v2 = a2 + bv.z, v3 = a3 + bv.w;
        sh[col]     = v0 > 0.f ? v0 : 0.f;
        sh[col + 1] = v1 > 0.f ? v1 : 0.f;
        sh[col + 2] = v2 > 0.f ? v2 : 0.f;
        sh[col + 3] = v3 > 0.f ? v3 : 0.f;
    }
    __syncthreads();

    // fused GEMM2: 64 threads (8 outputs x 8 k-segments of 25)
    {
        int o = tid & 7, seg = tid >> 3;
        float p = 0.f;
        int k0 = seg * 25;
#pragma unroll 5
        for (int k = k0; k < k0 + 25; k++)
            p += sh[k] * W2[k * OUT_DIM + o];
        psum[tid] = p;
    }
    __syncthreads();
    if (tid < OUT_DIM) {
        float s = 0.f;
#pragma unroll
        for (int j = 0; j < 8; j++) s += psum[j * 8 + tid];
        g_H2h[(size_t)n * OUT_DIM + tid] = __float2half_rn(s);
    }
}

// ---------------- propagation 2 (fp16 H2, 4-lane col pairs) ------------------
__global__ void prop2_kernel(const float* __restrict__ b2,
                             float* __restrict__ outp) {
    int n = blockIdx.x * 4 + (threadIdx.x >> 5);
    if (n >= N_NODES) return;
    int lane = threadIdx.x & 31;
    int grp = lane >> 2;      // 0..7 edge groups
    int c2  = lane & 3;       // column pair 2*c2, 2*c2+1
    float acc0 = 0.f, acc1 = 0.f;
    int beg = g_off[n], end = g_off[n + 1];
    for (int e = beg + grp; e < end; e += 8) {
        float w = g_csr_w[e];
        __half2 h = *reinterpret_cast<const __half2*>(
            g_H2h + (size_t)g_csr_src[e] * OUT_DIM + c2 * 2);
        float2 f = __half22float2(h);
        acc0 += f.x * w;
        acc1 += f.y * w;
    }
#pragma unroll
    for (int d = 16; d >= 4; d >>= 1) {
        acc0 += __shfl_xor_sync(0xffffffffu, acc0, d);
        acc1 += __shfl_xor_sync(0xffffffffu, acc1, d);
    }
    if (grp == 0) {
        float dv = g_dis[n];
        float s2 = dv * dv;
        float2 self = __half22float2(*reinterpret_cast<const __half2*>(
            g_H2h + (size_t)n * OUT_DIM + c2 * 2));
        outp[(size_t)n * OUT_DIM + c2 * 2]     = acc0 + self.x * s2 + b2[c2 * 2];
        outp[(size_t)n * OUT_DIM + c2 * 2 + 1] = acc1 + self.y * s2 + b2[c2 * 2 + 1];
    }
}

// ---------------- launch -----------------------------------------------------
extern "C" void kernel_launch(void* const* d_in, const int* in_sizes, int n_in,
                              void* d_out, int out_size) {
    const float* x  = (const float*)d_in[0];
    const float* ew = (const float*)d_in[1];
    const float* W1 = (const float*)d_in[2];
    const float* b1 = (const float*)d_in[3];
    const float* W2 = (const float*)d_in[4];
    const float* b2 = (const float*)d_in[5];
    const void*  ei = d_in[6];
    float* outp = (float*)d_out;

    static cudaStream_t s1 = nullptr;
    static cudaEvent_t evFork = nullptr, evJoin = nullptr;
    if (!s1) {
        cudaStreamCreateWithFlags(&s1, cudaStreamNonBlocking);
        cudaEventCreateWithFlags(&evFork, cudaEventDisableTiming);
        cudaEventCreateWithFlags(&evJoin, cudaEventDisableTiming);
        cudaFuncSetAttribute(gemm1_kernel,
                             cudaFuncAttributeMaxDynamicSharedMemorySize, G1_SMEM);
    }

    cudaEventRecord(evFork, 0);
    cudaStreamWaitEvent(s1, evFork, 0);

    detect_kernel<<<1, 256, 0, s1>>>((const unsigned*)ei, 4096);
    init_kernel<<<(N_NODES + 255) / 256, 256, 0, s1>>>();
    w1t_kernel<<<dim3((N_PAD + 31) / 32, (IN_DIM + 31) / 32), dim3(32, 8)>>>(W1);
    gemm1_kernel<<<(N_NODES + G1_BM - 1) / G1_BM, G1T, G1_SMEM>>>(x);
    accum_kernel<<<(N_EDGES + 255) / 256, 256, 0, s1>>>(ei, ew);
    rsqrt_kernel<<<(N_NODES + 255) / 256, 256, 0, s1>>>();
    scan_kernel<<<1, 1024, 0, s1>>>();
    fill_kernel<<<(N_EDGES + 255) / 256, 256, 0, s1>>>(ei, ew);

    cudaEventRecord(evJoin, s1);
    cudaStreamWaitEvent(0, evJoin, 0);

    prop1_kernel<<<N_NODES, 64>>>(b1, W2);
    prop2_kernel<<<(N_NODES + 3) / 4, 128>>>(b2, outp);
}

// round 16
// speedup vs baseline: 2.0914x; 1.0143x over previous
#include <cuda_runtime.h>
#include <cuda_fp16.h>
#include <cstdint>

#define N_NODES 50000
#define IN_DIM  7688
#define HID     200
#define N_PAD   224
#define OUT_DIM 8
#define N_EDGES 1600000

// ---------------- scratch (device globals; no allocation allowed) -------------
__device__ float  g_dis[N_NODES];
__device__ int    g_cnt[N_NODES];
__device__ int    g_off[N_NODES + 1];
__device__ int    g_cur[N_NODES];
__device__ int    g_csr_src[N_EDGES];
__device__ float  g_csr_w[N_EDGES];
__device__ __half g_W1h[(size_t)N_PAD * IN_DIM];    // W1^T fp16, [n][k], rows>=200 zero
__device__ __half g_H1h[(size_t)N_NODES * HID];     // H1 in fp16
__device__ __half g_H2h[(size_t)N_NODES * OUT_DIM]; // H2 in fp16
__device__ int    g_is64;

// ---------------- helpers ----------------------------------------------------
__device__ __forceinline__ int edge_at(const void* ei, size_t pos, int is64) {
    if (is64) return (int)((const long long*)ei)[pos];
    return ((const int*)ei)[pos];
}

__device__ __forceinline__ uint32_t smem_u32(const void* p) {
    uint32_t a;
    asm("{ .reg .u64 t; cvta.to.shared.u64 t, %1; cvt.u32.u64 %0, t; }"
        : "=r"(a) : "l"(p));
    return a;
}

__device__ __forceinline__ void cp16(uint32_t saddr, const void* g, int sz) {
    asm volatile("cp.async.cg.shared.global [%0], [%1], 16, %2;\n"
                 :: "r"(saddr), "l"(g), "r"(sz));
}

#define LDSM4(r0, r1, r2, r3, a)                                               \
    asm volatile("ldmatrix.sync.aligned.m8n8.x4.shared.b16 {%0,%1,%2,%3},[%4];"\
                 : "=r"(r0), "=r"(r1), "=r"(r2), "=r"(r3) : "r"(a))

#define LDSM2(r0, r1, a)                                                       \
    asm volatile("ldmatrix.sync.aligned.m8n8.x2.shared.b16 {%0,%1},[%2];"      \
                 : "=r"(r0), "=r"(r1) : "r"(a))

#define MMA16816(c, a, b)                                                      \
    asm volatile(                                                              \
        "mma.sync.aligned.m16n8k16.row.col.f32.f16.f16.f32 "                   \
        "{%0,%1,%2,%3},{%4,%5,%6,%7},{%8,%9},{%0,%1,%2,%3};\n"                 \
        : "+f"((c)[0]), "+f"((c)[1]), "+f"((c)[2]), "+f"((c)[3])               \
        : "r"((a)[0]), "r"((a)[1]), "r"((a)[2]), "r"((a)[3]),                  \
          "r"((b)[0]), "r"((b)[1]))

// ---------------- dtype detection --------------------------------------------
__global__ void detect_kernel(const unsigned* __restrict__ w, int n_check) {
    __shared__ int bad;
    if (threadIdx.x == 0) bad = 0;
    __syncthreads();
    int local = 0;
    for (int i = threadIdx.x; i < n_check; i += blockDim.x)
        if (w[2 * i + 1] != 0u) local = 1;
    if (local) bad = 1;
    __syncthreads();
    if (threadIdx.x == 0) g_is64 = bad ? 0 : 1;
}

// ---------------- degree + histogram init ------------------------------------
__global__ void init_kernel() {
    int i = blockIdx.x * blockDim.x + threadIdx.x;
    if (i < N_NODES) { g_dis[i] = 1.0f; g_cnt[i] = 0; }
}

// ---------------- W1 transpose + fp16 convert (padded to 224 rows) -----------
__global__ void w1t_kernel(const float* __restrict__ W1) {
    __shared__ float tile[32][33];
    int kb = blockIdx.y * 32, nb = blockIdx.x * 32;
    for (int j = threadIdx.y; j < 32; j += 8) {
        int k = kb + j, n = nb + threadIdx.x;
        tile[j][threadIdx.x] =
            (k < IN_DIM && n < HID) ? W1[(size_t)k * HID + n] : 0.f;
    }
    __syncthreads();
    for (int j = threadIdx.y; j < 32; j += 8) {
        int n = nb + j, k = kb + threadIdx.x;
        if (n < N_PAD && k < IN_DIM)
            g_W1h[(size_t)n * IN_DIM + k] = __float2half_rn(tile[threadIdx.x][j]);
    }
}

// ---------------- GEMM1: 128x224 CTA, BK=64, 8 warps (2x4), 1 CTA/SM ---------
#define G1T   256
#define G1_BM 128
#define G1_BK 64
#define G1_NT 121
#define SMA_BYTES (G1_BM * 128)
#define SMB_BYTES (N_PAD * 128)
#define G1_SMEM (2 * SMA_BYTES + 2 * SMB_BYTES)

__global__ __launch_bounds__(G1T, 1)
void gemm1_kernel(const float* __restrict__ X) {
    extern __shared__ __align__(16) unsigned char smem[];
    unsigned char* smA = smem;
    unsigned char* smB = smem + 2 * SMA_BYTES;
    const uint32_t smA0 = smem_u32(smA);
    const uint32_t smB0 = smem_u32(smB);

    const int tid  = threadIdx.x;
    const int lane = tid & 31;
    const int warp = tid >> 5;
    const int gid  = lane >> 2;
    const int tig  = lane & 3;
    const int wm   = warp >> 2;
    const int wn   = warp & 3;
    const int m0   = blockIdx.x * G1_BM;

    int aC[4];
    uint32_t aDst[4];
    bool aOkRow[4];
    const float* aSrc[4];
#pragma unroll
    for (int j = 0; j < 4; j++) {
        int idx = tid + j * G1T;
        int r = idx >> 3, c = idx & 7;
        aC[j] = c;
        aDst[j] = (uint32_t)(r * 128 + ((c ^ (r & 7)) << 4));
        aOkRow[j] = (m0 + r) < N_NODES;
        aSrc[j] = X + (size_t)(aOkRow[j] ? (m0 + r) : 0) * IN_DIM + c * 8;
    }

    float4 va[4][2];
    auto ldgA = [&](int k0) {
        const float4 z = make_float4(0.f, 0.f, 0.f, 0.f);
#pragma unroll
        for (int j = 0; j < 4; j++) {
            bool ok = aOkRow[j] && ((k0 + aC[j] * 8 + 8) <= IN_DIM);
            if (ok) {
                va[j][0] = *reinterpret_cast<const float4*>(aSrc[j] + k0);
                va[j][1] = *reinterpret_cast<const float4*>(aSrc[j] + k0 + 4);
            } else { va[j][0] = z; va[j][1] = z; }
        }
    };
    auto stsA = [&](int buf) {
        unsigned char* base = smA + buf * SMA_BYTES;
#pragma unroll
        for (int j = 0; j < 4; j++) {
            __half2 h0 = __floats2half2_rn(va[j][0].x, va[j][0].y);
            __half2 h1 = __floats2half2_rn(va[j][0].z, va[j][0].w);
            __half2 h2 = __floats2half2_rn(va[j][1].x, va[j][1].y);
            __half2 h3 = __floats2half2_rn(va[j][1].z, va[j][1].w);
            *reinterpret_cast<uint4*>(base + aDst[j]) =
                make_uint4(*(uint32_t*)&h0, *(uint32_t*)&h1,
                           *(uint32_t*)&h2, *(uint32_t*)&h3);
        }
    };
    auto cpB = [&](int k0, int buf) {
        const uint32_t bb = smB0 + (uint32_t)buf * SMB_BYTES;
#pragma unroll
        for (int j = 0; j < 7; j++) {
            int idx = tid + j * G1T;
            int n = idx >> 3, c = idx & 7;
            int ok = (k0 + c * 8 + 8) <= IN_DIM;
            const __half* src = g_W1h + (size_t)n * IN_DIM + (ok ? (k0 + c * 8) : 0);
            cp16(bb + (uint32_t)(n * 128 + ((c ^ (n & 7)) << 4)), src, ok ? 16 : 0);
        }
        asm volatile("cp.async.commit_group;\n");
    };

    uint32_t aRow[4];
#pragma unroll
    for (int mi = 0; mi < 4; mi++)
        aRow[mi] = (uint32_t)((wm * 64 + mi * 16 + (lane & 15)) * 128);
    uint32_t bRow4[3], bRow2;
#pragma unroll
    for (int p = 0; p < 3; p++)
        bRow4[p] = (uint32_t)((wn * 56 + p * 16 + (lane & 7) + ((lane >> 4) << 3)) * 128);
    bRow2 = (uint32_t)((wn * 56 + 48 + (lane & 7)) * 128);
    const int xorR  = lane & 7;
    const int khalf = (lane >> 3) & 1;
    const int khalfA = lane >> 4;

    float c[4][7][4];
#pragma unroll
    for (int mi = 0; mi < 4; mi++)
#pragma unroll
        for (int ni = 0; ni < 7; ni++)
#pragma unroll
            for (int r = 0; r < 4; r++) c[mi][ni][r] = 0.0f;

    ldgA(0);
    cpB(0, 0);
    stsA(0);
    asm volatile("cp.async.wait_group 0;\n");
    __syncthreads();

    for (int t = 0; t < G1_NT; t++) {
        const int buf = t & 1;
        const bool more = (t + 1) < G1_NT;
        if (more) {
            ldgA((t + 1) * G1_BK);
            cpB((t + 1) * G1_BK, buf ^ 1);
        }
        const uint32_t ab = smA0 + (uint32_t)buf * SMA_BYTES;
        const uint32_t bb = smB0 + (uint32_t)buf * SMB_BYTES;

        uint32_t a[2][4][4], b[2][7][2];
        auto loadF = [&](int ks, int set) {
            uint32_t aoff = (uint32_t)(((ks * 2 + khalfA) ^ xorR) << 4);
            uint32_t boff = (uint32_t)(((ks * 2 + khalf) ^ xorR) << 4);
#pragma unroll
            for (int mi = 0; mi < 4; mi++)
                LDSM4(a[set][mi][0], a[set][mi][1], a[set][mi][2], a[set][mi][3],
                      ab + aRow[mi] + aoff);
#pragma unroll
            for (int p = 0; p < 3; p++)
                LDSM4(b[set][2 * p][0], b[set][2 * p][1],
                      b[set][2 * p + 1][0], b[set][2 * p + 1][1],
                      bb + bRow4[p] + boff);
            LDSM2(b[set][6][0], b[set][6][1], bb + bRow2 + boff);
        };
        loadF(0, 0);
#pragma unroll
        for (int ks = 0; ks < 4; ks++) {
            const int cur = ks & 1;
            if (ks < 3) loadF(ks + 1, cur ^ 1);
            if (ks == 3 && more) {
                stsA(buf ^ 1);
                asm volatile("cp.async.wait_group 0;\n");
            }
#pragma unroll
            for (int mi = 0; mi < 4; mi++)
#pragma unroll
                for (int ni = 0; ni < 7; ni++)
                    MMA16816(c[mi][ni], a[cur][mi], b[cur][ni]);
        }
        __syncthreads();
    }

    // epilogue: store H1 as fp16 (mask cols >= 200)
#pragma unroll
    for (int mi = 0; mi < 4; mi++) {
        int r0 = m0 + wm * 64 + mi * 16 + gid;
        int r1 = r0 + 8;
#pragma unroll
        for (int ni = 0; ni < 7; ni++) {
            int col = wn * 56 + ni * 8 + 2 * tig;
            if (col >= HID) continue;
            if (r0 < N_NODES) {
                __half2 h = __floats2half2_rn(c[mi][ni][0], c[mi][ni][1]);
                *reinterpret_cast<__half2*>(g_H1h + (size_t)r0 * HID + col) = h;
            }
            if (r1 < N_NODES) {
                __half2 h = __floats2half2_rn(c[mi][ni][2], c[mi][ni][3]);
                *reinterpret_cast<__half2*>(g_H1h + (size_t)r1 * HID + col) = h;
            }
        }
    }
}

// ---------------- degree accumulate ------------------------------------------
__global__ void accum_kernel(const void* __restrict__ ei,
                             const float* __restrict__ ew) {
    int e = blockIdx.x * blockDim.x + threadIdx.x;
    if (e >= N_EDGES) return;
    int is64 = g_is64;
    int d = edge_at(ei, (size_t)N_EDGES + e, is64);
    atomicAdd(&g_dis[d], ew[e]);
    atomicAdd(&g_cnt[d], 1);
}

__global__ void rsqrt_kernel() {
    int i = blockIdx.x * blockDim.x + threadIdx.x;
    if (i < N_NODES) {
        float dg = g_dis[i];
        g_dis[i] = (dg > 0.0f) ? rsqrtf(dg) : 0.0f;
    }
}

// ---------------- exclusive scan (single block) ------------------------------
__global__ void scan_kernel() {
    __shared__ int part[1024];
    const int tid = threadIdx.x;
    const int CH = (N_NODES + 1023) / 1024;
    int base = tid * CH;
    int s = 0;
    for (int i = 0; i < CH; i++) {
        int idx = base + i;
        if (idx < N_NODES) s += g_cnt[idx];
    }
    part[tid] = s;
    __syncthreads();
    for (int off = 1; off < 1024; off <<= 1) {
        int v = (tid >= off) ? part[tid - off] : 0;
        __syncthreads();
        part[tid] += v;
        __syncthreads();
    }
    int ex = part[tid] - s;
    for (int i = 0; i < CH; i++) {
        int idx = base + i;
        if (idx < N_NODES) {
            g_off[idx] = ex;
            g_cur[idx] = ex;
            ex += g_cnt[idx];
        }
    }
    if (tid == 1023) g_off[N_NODES] = part[1023];
}

// ---------------- CSR fill ----------------------------------------------------
__global__ void fill_kernel(const void* __restrict__ ei,
                            const float* __restrict__ ew) {
    int e = blockIdx.x * blockDim.x + threadIdx.x;
    if (e >= N_EDGES) return;
    int is64 = g_is64;
    int s = edge_at(ei, e, is64);
    int d = edge_at(ei, (size_t)N_EDGES + e, is64);
    float w = g_dis[s] * ew[e] * g_dis[d];
    int pos = atomicAdd(&g_cur[d], 1);
    g_csr_src[pos] = s;
    g_csr_w[pos] = w;
}

// ---------------- prop1 (fp16 gather, 4 cols/thread, unroll-4) + GEMM2 -------
__global__ __launch_bounds__(64)
void prop1_kernel(const float* __restrict__ b1, const float* __restrict__ W2) {
    __shared__ float sh[HID];
    __shared__ float psum[64];
    const int n = blockIdx.x;
    const int tid = threadIdx.x;

    if (tid < HID / 4) {
        const int col = tid * 4;   // 4 halves = 8 bytes
        float dv = g_dis[n];
        float s2 = dv * dv;
        uint2 hv = *reinterpret_cast<const uint2*>(g_H1h + (size_t)n * HID + col);
        float2 ha = __half22float2(*(const __half2*)&hv.x);
        float2 hb = __half22float2(*(const __half2*)&hv.y);
        float a0 = ha.x * s2, a1 = ha.y * s2, a2 = hb.x * s2, a3 = hb.y * s2;
        int e = g_off[n], end = g_off[n + 1];
        // unroll-4: 4 independent gather chains per round (MLP ~8 with uint2x4)
        for (; e + 4 <= end; e += 4) {
            int s0 = g_csr_src[e],     s1 = g_csr_src[e + 1];
            int s_2 = g_csr_src[e + 2], s_3 = g_csr_src[e + 3];
            float w0 = g_csr_w[e],     w1 = g_csr_w[e + 1];
            float w2 = g_csr_w[e + 2], w3 = g_csr_w[e + 3];
            uint2 x0 = *reinterpret_cast<const uint2*>(g_H1h + (size_t)s0 * HID + col);
            uint2 x1 = *reinterpret_cast<const uint2*>(g_H1h + (size_t)s1 * HID + col);
            uint2 x2 = *reinterpret_cast<const uint2*>(g_H1h + (size_t)s_2 * HID + col);
            uint2 x3 = *reinterpret_cast<const uint2*>(g_H1h + (size_t)s_3 * HID + col);
            float2 x0a = __half22float2(*(const __half2*)&x0.x);
            float2 x0b = __half22float2(*(const __half2*)&x0.y);
            float2 x1a = __half22float2(*(const __half2*)&x1.x);
            float2 x1b = __half22float2(*(const __half2*)&x1.y);
            float2 x2a = __half22float2(*(const __half2*)&x2.x);
            float2 x2b = __half22float2(*(const __half2*)&x2.y);
            float2 x3a = __half22float2(*(const __half2*)&x3.x);
            float2 x3b = __half22float2(*(const __half2*)&x3.y);
            a0 += x0a.x * w0 + x1a.x * w1 + x2a.x * w2 + x3a.x * w3;
            a1 += x0a.y * w0 + x1a.y * w1 + x2a.y * w2 + x3a.y * w3;
            a2 += x0b.x * w0 + x1b.x * w1 + x2b.x * w2 + x3b.x * w3;
            a3 += x0b.y * w0 + x1b.y * w1 + x2b.y * w2 + x3b.y * w3;
        }
        for (; e < end; e++) {
            int s0 = g_csr_src[e];
            float w0 = g_csr_w[e];
            uint2 x0 = *reinterpret_cast<const uint2*>(g_H1h + (size_t)s0 * HID + col);
            float2 x0a = __half22float2(*(const __half2*)&x0.x);
            float2 x0b = __half22float2(*(const __half2*)&x0.y);
            a0 += x0a.x * w0; a1 += x0a.y * w0;
            a2 += x0b.x * w0; a3 += x0b.y * w0;
        }
        float4 bv = *reinterpret_cast<const float4*>(b1 + col);
        float v0 = a0 + bv.x, v1 = a1 + bv.y, v2 = a2 + bv.z, v3 = a3 + bv.w;
        sh[col]     = v0 > 0.f ? v0 : 0.f;
        sh[col + 1] = v1 > 0.f ? v1 : 0.f;
        sh[col + 2] = v2 > 0.f ? v2 : 0.f;
        sh[col + 3] = v3 > 0.f ? v3 : 0.f;
    }
    __syncthreads();

    // fused GEMM2: 64 threads (8 outputs x 8 k-segments of 25)
    {
        int o = tid & 7, seg = tid >> 3;
        float p = 0.f;
        int k0 = seg * 25;
#pragma unroll 5
        for (int k = k0; k < k0 + 25; k++)
            p += sh[k] * W2[k * OUT_DIM + o];
        psum[tid] = p;
    }
    __syncthreads();
    if (tid < OUT_DIM) {
        float s = 0.f;
#pragma unroll
        for (int j = 0; j < 8; j++) s += psum[j * 8 + tid];
        g_H2h[(size_t)n * OUT_DIM + tid] = __float2half_rn(s);
    }
}

// ---------------- propagation 2 (fp16 H2, 4-lane col pairs) ------------------
__global__ void prop2_kernel(const float* __restrict__ b2,
                             float* __restrict__ outp) {
    int n = blockIdx.x * 4 + (threadIdx.x >> 5);
    if (n >= N_NODES) return;
    int lane = threadIdx.x & 31;
    int grp = lane >> 2;      // 0..7 edge groups
    int c2  = lane & 3;       // column pair 2*c2, 2*c2+1
    float acc0 = 0.f, acc1 = 0.f;
    int beg = g_off[n], end = g_off[n + 1];
    for (int e = beg + grp; e < end; e += 8) {
        float w = g_csr_w[e];
        __half2 h = *reinterpret_cast<const __half2*>(
            g_H2h + (size_t)g_csr_src[e] * OUT_DIM + c2 * 2);
        float2 f = __half22float2(h);
        acc0 += f.x * w;
        acc1 += f.y * w;
    }
#pragma unroll
    for (int d = 16; d >= 4; d >>= 1) {
        acc0 += __shfl_xor_sync(0xffffffffu, acc0, d);
        acc1 += __shfl_xor_sync(0xffffffffu, acc1, d);
    }
    if (grp == 0) {
        float dv = g_dis[n];
        float s2 = dv * dv;
        float2 self = __half22float2(*reinterpret_cast<const __half2*>(
            g_H2h + (size_t)n * OUT_DIM + c2 * 2));
        outp[(size_t)n * OUT_DIM + c2 * 2]     = acc0 + self.x * s2 + b2[c2 * 2];
        outp[(size_t)n * OUT_DIM + c2 * 2 + 1] = acc1 + self.y * s2 + b2[c2 * 2 + 1];
    }
}

// ---------------- launch -----------------------------------------------------
extern "C" void kernel_launch(void* const* d_in, const int* in_sizes, int n_in,
                              void* d_out, int out_size) {
    const float* x  = (const float*)d_in[0];
    const float* ew = (const float*)d_in[1];
    const float* W1 = (const float*)d_in[2];
    const float* b1 = (const float*)d_in[3];
    const float* W2 = (const float*)d_in[4];
    const float* b2 = (const float*)d_in[5];
    const void*  ei = d_in[6];
    float* outp = (float*)d_out;

    static cudaStream_t s1 = nullptr;
    static cudaEvent_t evFork = nullptr, evJoin = nullptr;
    if (!s1) {
        cudaStreamCreateWithFlags(&s1, cudaStreamNonBlocking);
        cudaEventCreateWithFlags(&evFork, cudaEventDisableTiming);
        cudaEventCreateWithFlags(&evJoin, cudaEventDisableTiming);
        cudaFuncSetAttribute(gemm1_kernel,
                             cudaFuncAttributeMaxDynamicSharedMemorySize, G1_SMEM);
    }

    cudaEventRecord(evFork, 0);
    cudaStreamWaitEvent(s1, evFork, 0);

    detect_kernel<<<1, 256, 0, s1>>>((const unsigned*)ei, 4096);
    init_kernel<<<(N_NODES + 255) / 256, 256, 0, s1>>>();
    w1t_kernel<<<dim3((N_PAD + 31) / 32, (IN_DIM + 31) / 32), dim3(32, 8)>>>(W1);
    gemm1_kernel<<<(N_NODES + G1_BM - 1) / G1_BM, G1T, G1_SMEM>>>(x);
    accum_kernel<<<(N_EDGES + 255) / 256, 256, 0, s1>>>(ei, ew);
    rsqrt_kernel<<<(N_NODES + 255) / 256, 256, 0, s1>>>();
    scan_kernel<<<1, 1024, 0, s1>>>();
    fill_kernel<<<(N_EDGES + 255) / 256, 256, 0, s1>>>(ei, ew);

    cudaEventRecord(evJoin, s1);
    cudaStreamWaitEvent(0, evJoin, 0);

    prop1_kernel<<<N_NODES, 64>>>(b1, W2);
    prop2_kernel<<<(N_NODES + 3) / 4, 128>>>(b2, outp);
}

// round 17
// speedup vs baseline: 2.0941x; 1.0013x over previous
#include <cuda_runtime.h>
#include <cuda_fp16.h>
#include <cstdint>

#define N_NODES 50000
#define IN_DIM  7688
#define HID     200
#define N_PAD   224
#define OUT_DIM 8
#define N_EDGES 1600000

// ---------------- scratch (device globals; no allocation allowed) -------------
__device__ float  g_dis[N_NODES];
__device__ int    g_cnt[N_NODES];
__device__ int    g_off[N_NODES + 1];
__device__ int    g_cur[N_NODES];
__device__ int    g_csr_src[N_EDGES];
__device__ float  g_csr_w[N_EDGES];
__device__ __half g_W1h[(size_t)N_PAD * IN_DIM];    // W1^T fp16, [n][k], rows>=200 zero
__device__ __half g_H1h[(size_t)N_NODES * HID];     // H1 in fp16
__device__ __half g_H2h[(size_t)N_NODES * OUT_DIM]; // H2 in fp16
__device__ int    g_is64;

// ---------------- helpers ----------------------------------------------------
__device__ __forceinline__ int edge_at(const void* ei, size_t pos, int is64) {
    if (is64) return (int)((const long long*)ei)[pos];
    return ((const int*)ei)[pos];
}

__device__ __forceinline__ uint32_t smem_u32(const void* p) {
    uint32_t a;
    asm("{ .reg .u64 t; cvta.to.shared.u64 t, %1; cvt.u32.u64 %0, t; }"
        : "=r"(a) : "l"(p));
    return a;
}

__device__ __forceinline__ void cp16(uint32_t saddr, const void* g, int sz) {
    asm volatile("cp.async.cg.shared.global [%0], [%1], 16, %2;\n"
                 :: "r"(saddr), "l"(g), "r"(sz));
}

#define LDSM4(r0, r1, r2, r3, a)                                               \
    asm volatile("ldmatrix.sync.aligned.m8n8.x4.shared.b16 {%0,%1,%2,%3},[%4];"\
                 : "=r"(r0), "=r"(r1), "=r"(r2), "=r"(r3) : "r"(a))

#define LDSM2(r0, r1, a)                                                       \
    asm volatile("ldmatrix.sync.aligned.m8n8.x2.shared.b16 {%0,%1},[%2];"      \
                 : "=r"(r0), "=r"(r1) : "r"(a))

#define MMA16816(c, a, b)                                                      \
    asm volatile(                                                              \
        "mma.sync.aligned.m16n8k16.row.col.f32.f16.f16.f32 "                   \
        "{%0,%1,%2,%3},{%4,%5,%6,%7},{%8,%9},{%0,%1,%2,%3};\n"                 \
        : "+f"((c)[0]), "+f"((c)[1]), "+f"((c)[2]), "+f"((c)[3])               \
        : "r"((a)[0]), "r"((a)[1]), "r"((a)[2]), "r"((a)[3]),                  \
          "r"((b)[0]), "r"((b)[1]))

// ---------------- dtype detection --------------------------------------------
__global__ void detect_kernel(const unsigned* __restrict__ w, int n_check) {
    __shared__ int bad;
    if (threadIdx.x == 0) bad = 0;
    __syncthreads();
    int local = 0;
    for (int i = threadIdx.x; i < n_check; i += blockDim.x)
        if (w[2 * i + 1] != 0u) local = 1;
    if (local) bad = 1;
    __syncthreads();
    if (threadIdx.x == 0) g_is64 = bad ? 0 : 1;
}

// ---------------- degree + histogram init ------------------------------------
__global__ void init_kernel() {
    int i = blockIdx.x * blockDim.x + threadIdx.x;
    if (i < N_NODES) { g_dis[i] = 1.0f; g_cnt[i] = 0; }
}

// ---------------- W1 transpose + fp16 convert (padded to 224 rows) -----------
__global__ void w1t_kernel(const float* __restrict__ W1) {
    __shared__ float tile[32][33];
    int kb = blockIdx.y * 32, nb = blockIdx.x * 32;
    for (int j = threadIdx.y; j < 32; j += 8) {
        int k = kb + j, n = nb + threadIdx.x;
        tile[j][threadIdx.x] =
            (k < IN_DIM && n < HID) ? W1[(size_t)k * HID + n] : 0.f;
    }
    __syncthreads();
    for (int j = threadIdx.y; j < 32; j += 8) {
        int n = nb + j, k = kb + threadIdx.x;
        if (n < N_PAD && k < IN_DIM)
            g_W1h[(size_t)n * IN_DIM + k] = __float2half_rn(tile[threadIdx.x][j]);
    }
}

// ---------------- GEMM1: 128x224 CTA, BK=64, 8 warps (2x4), 1 CTA/SM ---------
#define G1T   256
#define G1_BM 128
#define G1_BK 64
#define G1_NT 121
#define SMA_BYTES (G1_BM * 128)
#define SMB_BYTES (N_PAD * 128)
#define G1_SMEM (2 * SMA_BYTES + 2 * SMB_BYTES)

__global__ __launch_bounds__(G1T, 1)
void gemm1_kernel(const float* __restrict__ X) {
    extern __shared__ __align__(16) unsigned char smem[];
    unsigned char* smA = smem;
    unsigned char* smB = smem + 2 * SMA_BYTES;
    const uint32_t smA0 = smem_u32(smA);
    const uint32_t smB0 = smem_u32(smB);

    const int tid  = threadIdx.x;
    const int lane = tid & 31;
    const int warp = tid >> 5;
    const int gid  = lane >> 2;
    const int tig  = lane & 3;
    const int wm   = warp >> 2;
    const int wn   = warp & 3;
    const int m0   = blockIdx.x * G1_BM;

    int aC[4];
    uint32_t aDst[4];
    bool aOkRow[4];
    const float* aSrc[4];
#pragma unroll
    for (int j = 0; j < 4; j++) {
        int idx = tid + j * G1T;
        int r = idx >> 3, c = idx & 7;
        aC[j] = c;
        aDst[j] = (uint32_t)(r * 128 + ((c ^ (r & 7)) << 4));
        aOkRow[j] = (m0 + r) < N_NODES;
        aSrc[j] = X + (size_t)(aOkRow[j] ? (m0 + r) : 0) * IN_DIM + c * 8;
    }

    float4 va[4][2];
    auto ldgA = [&](int k0) {
        const float4 z = make_float4(0.f, 0.f, 0.f, 0.f);
#pragma unroll
        for (int j = 0; j < 4; j++) {
            bool ok = aOkRow[j] && ((k0 + aC[j] * 8 + 8) <= IN_DIM);
            if (ok) {
                va[j][0] = *reinterpret_cast<const float4*>(aSrc[j] + k0);
                va[j][1] = *reinterpret_cast<const float4*>(aSrc[j] + k0 + 4);
            } else { va[j][0] = z; va[j][1] = z; }
        }
    };
    auto stsA = [&](int buf) {
        unsigned char* base = smA + buf * SMA_BYTES;
#pragma unroll
        for (int j = 0; j < 4; j++) {
            __half2 h0 = __floats2half2_rn(va[j][0].x, va[j][0].y);
            __half2 h1 = __floats2half2_rn(va[j][0].z, va[j][0].w);
            __half2 h2 = __floats2half2_rn(va[j][1].x, va[j][1].y);
            __half2 h3 = __floats2half2_rn(va[j][1].z, va[j][1].w);
            *reinterpret_cast<uint4*>(base + aDst[j]) =
                make_uint4(*(uint32_t*)&h0, *(uint32_t*)&h1,
                           *(uint32_t*)&h2, *(uint32_t*)&h3);
        }
    };
    auto cpB = [&](int k0, int buf) {
        const uint32_t bb = smB0 + (uint32_t)buf * SMB_BYTES;
#pragma unroll
        for (int j = 0; j < 7; j++) {
            int idx = tid + j * G1T;
            int n = idx >> 3, c = idx & 7;
            int ok = (k0 + c * 8 + 8) <= IN_DIM;
            const __half* src = g_W1h + (size_t)n * IN_DIM + (ok ? (k0 + c * 8) : 0);
            cp16(bb + (uint32_t)(n * 128 + ((c ^ (n & 7)) << 4)), src, ok ? 16 : 0);
        }
        asm volatile("cp.async.commit_group;\n");
    };

    uint32_t aRow[4];
#pragma unroll
    for (int mi = 0; mi < 4; mi++)
        aRow[mi] = (uint32_t)((wm * 64 + mi * 16 + (lane & 15)) * 128);
    uint32_t bRow4[3], bRow2;
#pragma unroll
    for (int p = 0; p < 3; p++)
        bRow4[p] = (uint32_t)((wn * 56 + p * 16 + (lane & 7) + ((lane >> 4) << 3)) * 128);
    bRow2 = (uint32_t)((wn * 56 + 48 + (lane & 7)) * 128);
    const int xorR  = lane & 7;
    const int khalf = (lane >> 3) & 1;
    const int khalfA = lane >> 4;

    float c[4][7][4];
#pragma unroll
    for (int mi = 0; mi < 4; mi++)
#pragma unroll
        for (int ni = 0; ni < 7; ni++)
#pragma unroll
            for (int r = 0; r < 4; r++) c[mi][ni][r] = 0.0f;

    ldgA(0);
    cpB(0, 0);
    stsA(0);
    asm volatile("cp.async.wait_group 0;\n");
    __syncthreads();

    for (int t = 0; t < G1_NT; t++) {
        const int buf = t & 1;
        const bool more = (t + 1) < G1_NT;
        if (more) {
            ldgA((t + 1) * G1_BK);
            cpB((t + 1) * G1_BK, buf ^ 1);
        }
        const uint32_t ab = smA0 + (uint32_t)buf * SMA_BYTES;
        const uint32_t bb = smB0 + (uint32_t)buf * SMB_BYTES;

        uint32_t a[2][4][4], b[2][7][2];
        auto loadF = [&](int ks, int set) {
            uint32_t aoff = (uint32_t)(((ks * 2 + khalfA) ^ xorR) << 4);
            uint32_t boff = (uint32_t)(((ks * 2 + khalf) ^ xorR) << 4);
#pragma unroll
            for (int mi = 0; mi < 4; mi++)
                LDSM4(a[set][mi][0], a[set][mi][1], a[set][mi][2], a[set][mi][3],
                      ab + aRow[mi] + aoff);
#pragma unroll
            for (int p = 0; p < 3; p++)
                LDSM4(b[set][2 * p][0], b[set][2 * p][1],
                      b[set][2 * p + 1][0], b[set][2 * p + 1][1],
                      bb + bRow4[p] + boff);
            LDSM2(b[set][6][0], b[set][6][1], bb + bRow2 + boff);
        };
        loadF(0, 0);
#pragma unroll
        for (int ks = 0; ks < 4; ks++) {
            const int cur = ks & 1;
            if (ks < 3) loadF(ks + 1, cur ^ 1);
            if (ks == 3 && more) {
                stsA(buf ^ 1);
                asm volatile("cp.async.wait_group 0;\n");
            }
#pragma unroll
            for (int mi = 0; mi < 4; mi++)
#pragma unroll
                for (int ni = 0; ni < 7; ni++)
                    MMA16816(c[mi][ni], a[cur][mi], b[cur][ni]);
        }
        __syncthreads();
    }

    // epilogue: store H1 as fp16 (mask cols >= 200)
#pragma unroll
    for (int mi = 0; mi < 4; mi++) {
        int r0 = m0 + wm * 64 + mi * 16 + gid;
        int r1 = r0 + 8;
#pragma unroll
        for (int ni = 0; ni < 7; ni++) {
            int col = wn * 56 + ni * 8 + 2 * tig;
            if (col >= HID) continue;
            if (r0 < N_NODES) {
                __half2 h = __floats2half2_rn(c[mi][ni][0], c[mi][ni][1]);
                *reinterpret_cast<__half2*>(g_H1h + (size_t)r0 * HID + col) = h;
            }
            if (r1 < N_NODES) {
                __half2 h = __floats2half2_rn(c[mi][ni][2], c[mi][ni][3]);
                *reinterpret_cast<__half2*>(g_H1h + (size_t)r1 * HID + col) = h;
            }
        }
    }
}

// ---------------- degree accumulate ------------------------------------------
__global__ void accum_kernel(const void* __restrict__ ei,
                             const float* __restrict__ ew) {
    int e = blockIdx.x * blockDim.x + threadIdx.x;
    if (e >= N_EDGES) return;
    int is64 = g_is64;
    int d = edge_at(ei, (size_t)N_EDGES + e, is64);
    atomicAdd(&g_dis[d], ew[e]);
    atomicAdd(&g_cnt[d], 1);
}

__global__ void rsqrt_kernel() {
    int i = blockIdx.x * blockDim.x + threadIdx.x;
    if (i < N_NODES) {
        float dg = g_dis[i];
        g_dis[i] = (dg > 0.0f) ? rsqrtf(dg) : 0.0f;
    }
}

// ---------------- exclusive scan (single block) ------------------------------
__global__ void scan_kernel() {
    __shared__ int part[1024];
    const int tid = threadIdx.x;
    const int CH = (N_NODES + 1023) / 1024;
    int base = tid * CH;
    int s = 0;
    for (int i = 0; i < CH; i++) {
        int idx = base + i;
        if (idx < N_NODES) s += g_cnt[idx];
    }
    part[tid] = s;
    __syncthreads();
    for (int off = 1; off < 1024; off <<= 1) {
        int v = (tid >= off) ? part[tid - off] : 0;
        __syncthreads();
        part[tid] += v;
        __syncthreads();
    }
    int ex = part[tid] - s;
    for (int i = 0; i < CH; i++) {
        int idx = base + i;
        if (idx < N_NODES) {
            g_off[idx] = ex;
            g_cur[idx] = ex;
            ex += g_cnt[idx];
        }
    }
    if (tid == 1023) g_off[N_NODES] = part[1023];
}

// ---------------- CSR fill ----------------------------------------------------
__global__ void fill_kernel(const void* __restrict__ ei,
                            const float* __restrict__ ew) {
    int e = blockIdx.x * blockDim.x + threadIdx.x;
    if (e >= N_EDGES) return;
    int is64 = g_is64;
    int s = edge_at(ei, e, is64);
    int d = edge_at(ei, (size_t)N_EDGES + e, is64);
    float w = g_dis[s] * ew[e] * g_dis[d];
    int pos = atomicAdd(&g_cur[d], 1);
    g_csr_src[pos] = s;
    g_csr_w[pos] = w;
}

// ---------------- prop1 (fp16 gather, 4 cols/thread, unroll-8) + GEMM2 -------
__global__ __launch_bounds__(64)
void prop1_kernel(const float* __restrict__ b1, const float* __restrict__ W2) {
    __shared__ float sh[HID];
    __shared__ float psum[64];
    const int n = blockIdx.x;
    const int tid = threadIdx.x;

    if (tid < HID / 4) {
        const int col = tid * 4;   // 4 halves = 8 bytes
        float dv = g_dis[n];
        float s2 = dv * dv;
        uint2 hv = *reinterpret_cast<const uint2*>(g_H1h + (size_t)n * HID + col);
        float2 ha = __half22float2(*(const __half2*)&hv.x);
        float2 hb = __half22float2(*(const __half2*)&hv.y);
        float a0 = ha.x * s2, a1 = ha.y * s2, a2 = hb.x * s2, a3 = hb.y * s2;
        int e = g_off[n], end = g_off[n + 1];
        // unroll-8: 8 independent gather chains per round
        for (; e + 8 <= end; e += 8) {
            int si[8];
            float wi[8];
            uint2 xi[8];
#pragma unroll
            for (int j = 0; j < 8; j++) {
                si[j] = g_csr_src[e + j];
                wi[j] = g_csr_w[e + j];
            }
#pragma unroll
            for (int j = 0; j < 8; j++)
                xi[j] = *reinterpret_cast<const uint2*>(
                    g_H1h + (size_t)si[j] * HID + col);
#pragma unroll
            for (int j = 0; j < 8; j++) {
                float2 xa = __half22float2(*(const __half2*)&xi[j].x);
                float2 xb = __half22float2(*(const __half2*)&xi[j].y);
                a0 += xa.x * wi[j];
                a1 += xa.y * wi[j];
                a2 += xb.x * wi[j];
                a3 += xb.y * wi[j];
            }
        }
        for (; e < end; e++) {
            int s0 = g_csr_src[e];
            float w0 = g_csr_w[e];
            uint2 x0 = *reinterpret_cast<const uint2*>(g_H1h + (size_t)s0 * HID + col);
            float2 x0a = __half22float2(*(const __half2*)&x0.x);
            float2 x0b = __half22float2(*(const __half2*)&x0.y);
            a0 += x0a.x * w0; a1 += x0a.y * w0;
            a2 += x0b.x * w0; a3 += x0b.y * w0;
        }
        float4 bv = *reinterpret_cast<const float4*>(b1 + col);
        float v0 = a0 + bv.x, v1 = a1 + bv.y, v2 = a2 + bv.z, v3 = a3 + bv.w;
        sh[col]     = v0 > 0.f ? v0 : 0.f;
        sh[col + 1] = v1 > 0.f ? v1 : 0.f;
        sh[col + 2] = v2 > 0.f ? v2 : 0.f;
        sh[col + 3] = v3 > 0.f ? v3 : 0.f;
    }
    __syncthreads();

    // fused GEMM2: 64 threads (8 outputs x 8 k-segments of 25)
    {
        int o = tid & 7, seg = tid >> 3;
        float p = 0.f;
        int k0 = seg * 25;
#pragma unroll 5
        for (int k = k0; k < k0 + 25; k++)
            p += sh[k] * W2[k * OUT_DIM + o];
        psum[tid] = p;
    }
    __syncthreads();
    if (tid < OUT_DIM) {
        float s = 0.f;
#pragma unroll
        for (int j = 0; j < 8; j++) s += psum[j * 8 + tid];
        g_H2h[(size_t)n * OUT_DIM + tid] = __float2half_rn(s);
    }
}

// ---------------- propagation 2 (fp16 H2, 4-lane col pairs, unroll-2) --------
__global__ void prop2_kernel(const float* __restrict__ b2,
                             float* __restrict__ outp) {
    int n = blockIdx.x * 4 + (threadIdx.x >> 5);
    if (n >= N_NODES) return;
    int lane = threadIdx.x & 31;
    int grp = lane >> 2;      // 0..7 edge groups
    int c2  = lane & 3;       // column pair 2*c2, 2*c2+1
    float acc0 = 0.f, acc1 = 0.f;
    int beg = g_off[n], end = g_off[n + 1];
    int e = beg + grp;
    // unroll-2: two independent gathers per round
    for (; e + 8 < end; e += 16) {
        float w0 = g_csr_w[e];
        float w1 = g_csr_w[e + 8];
        int s0 = g_csr_src[e];
        int s1 = g_csr_src[e + 8];
        __half2 h0 = *reinterpret_cast<const __half2*>(
            g_H2h + (size_t)s0 * OUT_DIM + c2 * 2);
        __half2 h1 = *reinterpret_cast<const __half2*>(
            g_H2h + (size_t)s1 * OUT_DIM + c2 * 2);
        float2 f0 = __half22float2(h0);
        float2 f1 = __half22float2(h1);
        acc0 += f0.x * w0 + f1.x * w1;
        acc1 += f0.y * w0 + f1.y * w1;
    }
    for (; e < end; e += 8) {
        float w = g_csr_w[e];
        __half2 h = *reinterpret_cast<const __half2*>(
            g_H2h + (size_t)g_csr_src[e] * OUT_DIM + c2 * 2);
        float2 f = __half22float2(h);
        acc0 += f.x * w;
        acc1 += f.y * w;
    }
#pragma unroll
    for (int d = 16; d >= 4; d >>= 1) {
        acc0 += __shfl_xor_sync(0xffffffffu, acc0, d);
        acc1 += __shfl_xor_sync(0xffffffffu, acc1, d);
    }
    if (grp == 0) {
        float dv = g_dis[n];
        float s2 = dv * dv;
        float2 self = __half22float2(*reinterpret_cast<const __half2*>(
            g_H2h + (size_t)n * OUT_DIM + c2 * 2));
        outp[(size_t)n * OUT_DIM + c2 * 2]     = acc0 + self.x * s2 + b2[c2 * 2];
        outp[(size_t)n * OUT_DIM + c2 * 2 + 1] = acc1 + self.y * s2 + b2[c2 * 2 + 1];
    }
}

// ---------------- launch -----------------------------------------------------
extern "C" void kernel_launch(void* const* d_in, const int* in_sizes, int n_in,
                              void* d_out, int out_size) {
    const float* x  = (const float*)d_in[0];
    const float* ew = (const float*)d_in[1];
    const float* W1 = (const float*)d_in[2];
    const float* b1 = (const float*)d_in[3];
    const float* W2 = (const float*)d_in[4];
    const float* b2 = (const float*)d_in[5];
    const void*  ei = d_in[6];
    float* outp = (float*)d_out;

    static cudaStream_t s1 = nullptr;
    static cudaEvent_t evFork = nullptr, evJoin = nullptr;
    if (!s1) {
        cudaStreamCreateWithFlags(&s1, cudaStreamNonBlocking);
        cudaEventCreateWithFlags(&evFork, cudaEventDisableTiming);
        cudaEventCreateWithFlags(&evJoin, cudaEventDisableTiming);
        cudaFuncSetAttribute(gemm1_kernel,
                             cudaFuncAttributeMaxDynamicSharedMemorySize, G1_SMEM);
    }

    cudaEventRecord(evFork, 0);
    cudaStreamWaitEvent(s1, evFork, 0);

    detect_kernel<<<1, 256, 0, s1>>>((const unsigned*)ei, 4096);
    init_kernel<<<(N_NODES + 255) / 256, 256, 0, s1>>>();
    w1t_kernel<<<dim3((N_PAD + 31) / 32, (IN_DIM + 31) / 32), dim3(32, 8)>>>(W1);
    gemm1_kernel<<<(N_NODES + G1_BM - 1) / G1_BM, G1T, G1_SMEM>>>(x);
    accum_kernel<<<(N_EDGES + 255) / 256, 256, 0, s1>>>(ei, ew);
    rsqrt_kernel<<<(N_NODES + 255) / 256, 256, 0, s1>>>();
    scan_kernel<<<1, 1024, 0, s1>>>();
    fill_kernel<<<(N_EDGES + 255) / 256, 256, 0, s1>>>(ei, ew);

    cudaEventRecord(evJoin, s1);
    cudaStreamWaitEvent(0, evJoin, 0);

    prop1_kernel<<<N_NODES, 64>>>(b1, W2);
    prop2_kernel<<<(N_NODES + 3) / 4, 128>>>(b2, outp);
}